// round 1
// baseline (speedup 1.0000x reference)
#include <cuda_runtime.h>
#include <math.h>

#define Bc  4
#define Tc  2048
#define Dc  1024
#define Hc  8
#define HDc 128
#define Mc  (Bc*Tc)

// Scratch: Q, K, V, ctx in [B, H, T, HD] layout. 33.5MB each.
__device__ float g_q[Bc*Tc*Dc];
__device__ float g_k[Bc*Tc*Dc];
__device__ float g_v[Bc*Tc*Dc];
__device__ float g_ctx[Bc*Tc*Dc];

// ---------------------------------------------------------------------------
// SGEMM: out[m,n] = sum_k A[m,k] * W[n,k] + bias[n]
// MODE 0: A is plain [M,K], out is written in head layout [B,H,T,HD] to SEL
//         (0 -> g_q, 1 -> g_k, 2 -> g_v)
// MODE 1: A is gathered from g_ctx head layout, out is plain [M,N]
// Block: 128x128 tile, BK=8, 256 threads, 8x8 per thread.
// ---------------------------------------------------------------------------
template<int MODE, int SEL>
__global__ __launch_bounds__(256)
void gemm_abt(const float* __restrict__ Ain, const float* __restrict__ W,
              const float* __restrict__ bias, float* __restrict__ outp)
{
    __shared__ __align__(16) float As[8][132];
    __shared__ __align__(16) float Ws[8][132];

    const int tid  = threadIdx.x;
    const int bm   = blockIdx.y * 128;
    const int bn   = blockIdx.x * 128;
    const int ty   = tid >> 4;        // 0..15 -> m sub-rows
    const int tx   = tid & 15;        // 0..15 -> n sub-cols
    const int lrow = tid >> 1;        // 0..127
    const int lk4  = (tid & 1) * 4;   // 0 or 4

    const float* A = (MODE == 0) ? Ain : (const float*)g_ctx;
    float* out = (MODE == 0) ? (SEL == 0 ? g_q : (SEL == 1 ? g_k : g_v)) : outp;

    float acc[8][8];
#pragma unroll
    for (int i = 0; i < 8; i++)
#pragma unroll
        for (int j = 0; j < 8; j++) acc[i][j] = 0.f;

    const int m_l = bm + lrow;
    const int bl  = m_l / Tc;
    const int tl  = m_l % Tc;
    const int n_l = bn + lrow;

    for (int k0 = 0; k0 < Dc; k0 += 8) {
        const int ka = k0 + lk4;
        const float* aptr;
        if (MODE == 0) {
            aptr = A + (size_t)m_l * Dc + ka;
        } else {
            const int h = ka >> 7, d = ka & 127;
            aptr = A + ((((size_t)bl*Hc + h)*Tc + tl)*HDc + d);
        }
        const float4 av = *(const float4*)aptr;
        const float4 wv = *(const float4*)(W + (size_t)n_l * Dc + ka);
        As[lk4+0][lrow] = av.x; As[lk4+1][lrow] = av.y;
        As[lk4+2][lrow] = av.z; As[lk4+3][lrow] = av.w;
        Ws[lk4+0][lrow] = wv.x; Ws[lk4+1][lrow] = wv.y;
        Ws[lk4+2][lrow] = wv.z; Ws[lk4+3][lrow] = wv.w;
        __syncthreads();
#pragma unroll
        for (int kk = 0; kk < 8; kk++) {
            float a[8], w[8];
            *(float4*)&a[0] = *(const float4*)&As[kk][8*ty];
            *(float4*)&a[4] = *(const float4*)&As[kk][8*ty+4];
            *(float4*)&w[0] = *(const float4*)&Ws[kk][8*tx];
            *(float4*)&w[4] = *(const float4*)&Ws[kk][8*tx+4];
#pragma unroll
            for (int i = 0; i < 8; i++)
#pragma unroll
                for (int j = 0; j < 8; j++)
                    acc[i][j] += a[i]*w[j];
        }
        __syncthreads();
    }

#pragma unroll
    for (int i = 0; i < 8; i++) {
        const int m = bm + 8*ty + i;
        const int b = m / Tc, t = m % Tc;
#pragma unroll
        for (int j = 0; j < 8; j++) {
            const int n = bn + 8*tx + j;
            const float v = acc[i][j] + bias[n];
            if (MODE == 0) {
                const int h = n >> 7, d = n & 127;
                out[(((size_t)b*Hc + h)*Tc + t)*HDc + d] = v;
            } else {
                out[(size_t)m * Dc + n] = v;
            }
        }
    }
}

// ---------------------------------------------------------------------------
// Flash attention (fp32, causal). One block = 64 query rows of one (b,h).
// 256 threads: (ty,tx) in 16x16; each thread owns 4 q-rows x 4 k-cols of S
// and 4 q-rows x 8 d-cols of O.
// Shared: Qs[64][132], KV union (K as [128][68] d-major / V as [64][128]),
// Ps[64][68]. 84KB dynamic -> 2 blocks/SM.
// ---------------------------------------------------------------------------
#define FLASH_SMEM ((64*132 + 128*68 + 64*68) * 4)

__global__ __launch_bounds__(256)
void flash_attn()
{
    extern __shared__ __align__(16) float smem[];
    float* Qs = smem;                  // [64][132]
    float* KV = smem + 64*132;         // K: [128][68] (d-major) / V: [64][128]
    float* Ps = KV + 128*68;           // [64][68]

    const int bh    = blockIdx.y;
    const int qt    = blockIdx.x;
    const int qbase = qt * 64;
    const int tid   = threadIdx.x;
    const int ty    = tid >> 4;
    const int tx    = tid & 15;

    const float* Q  = g_q  + (size_t)bh * Tc * HDc;
    const float* Kg = g_k  + (size_t)bh * Tc * HDc;
    const float* Vg = g_v  + (size_t)bh * Tc * HDc;
    float*       Og = g_ctx + (size_t)bh * Tc * HDc;

    // Load Q tile (coalesced float4)
    for (int idx = tid; idx < 64*32; idx += 256) {
        const int r = idx >> 5, c4 = (idx & 31) << 2;
        *(float4*)&Qs[r*132 + c4] =
            *(const float4*)(Q + (size_t)(qbase + r)*HDc + c4);
    }

    float m_i[4], l_i[4], o[4][8];
#pragma unroll
    for (int i = 0; i < 4; i++) {
        m_i[i] = -1e30f; l_i[i] = 0.f;
#pragma unroll
        for (int c = 0; c < 8; c++) o[i][c] = 0.f;
    }

    const float scale = 0.08838834764831845f;  // 1/sqrt(128)

    for (int kt = 0; kt <= qt; kt++) {
        const int kbase = kt * 64;
        __syncthreads();  // prev PV done with KV(V); Q load done (kt=0)

        // Load K tile transposed: KV[d*68 + c] = K[kbase+c][d]
        for (int idx = tid; idx < 2048; idx += 256) {
            const int c = idx & 63, dg = idx >> 6;
            const float4 kv =
                *(const float4*)(Kg + (size_t)(kbase + c)*HDc + dg*4);
            KV[(dg*4+0)*68 + c] = kv.x;
            KV[(dg*4+1)*68 + c] = kv.y;
            KV[(dg*4+2)*68 + c] = kv.z;
            KV[(dg*4+3)*68 + c] = kv.w;
        }
        __syncthreads();

        // S = Q K^T (4x4 per thread)
        float s[4][4];
#pragma unroll
        for (int i = 0; i < 4; i++)
#pragma unroll
            for (int j = 0; j < 4; j++) s[i][j] = 0.f;

#pragma unroll 4
        for (int d = 0; d < 128; d++) {
            const float4 kx = *(const float4*)&KV[d*68 + 4*tx];
            const float q0 = Qs[(4*ty+0)*132 + d];
            const float q1 = Qs[(4*ty+1)*132 + d];
            const float q2 = Qs[(4*ty+2)*132 + d];
            const float q3 = Qs[(4*ty+3)*132 + d];
            s[0][0] += q0*kx.x; s[0][1] += q0*kx.y; s[0][2] += q0*kx.z; s[0][3] += q0*kx.w;
            s[1][0] += q1*kx.x; s[1][1] += q1*kx.y; s[1][2] += q1*kx.z; s[1][3] += q1*kx.w;
            s[2][0] += q2*kx.x; s[2][1] += q2*kx.y; s[2][2] += q2*kx.z; s[2][3] += q2*kx.w;
            s[3][0] += q3*kx.x; s[3][1] += q3*kx.y; s[3][2] += q3*kx.z; s[3][3] += q3*kx.w;
        }

        // Scale + causal mask (only the diagonal tile needs masking)
        const bool diag = (kt == qt);
#pragma unroll
        for (int i = 0; i < 4; i++) {
            const int qg = qbase + 4*ty + i;
#pragma unroll
            for (int j = 0; j < 4; j++) {
                float v = s[i][j] * scale;
                if (diag && (kbase + 4*tx + j > qg)) v = -1e30f;
                s[i][j] = v;
            }
        }

        // Online softmax per row; P -> shared
#pragma unroll
        for (int i = 0; i < 4; i++) {
            float mx = fmaxf(fmaxf(s[i][0], s[i][1]), fmaxf(s[i][2], s[i][3]));
#pragma unroll
            for (int off = 8; off >= 1; off >>= 1)
                mx = fmaxf(mx, __shfl_xor_sync(0xffffffffu, mx, off, 16));
            const float mnew  = fmaxf(m_i[i], mx);
            const float alpha = expf(m_i[i] - mnew);
            float psum = 0.f;
#pragma unroll
            for (int j = 0; j < 4; j++) {
                const float p = expf(s[i][j] - mnew);
                s[i][j] = p;
                psum += p;
            }
#pragma unroll
            for (int off = 8; off >= 1; off >>= 1)
                psum += __shfl_xor_sync(0xffffffffu, psum, off, 16);
            l_i[i] = l_i[i]*alpha + psum;
            m_i[i] = mnew;
#pragma unroll
            for (int c = 0; c < 8; c++) o[i][c] *= alpha;
#pragma unroll
            for (int j = 0; j < 4; j++)
                Ps[(4*ty+i)*68 + 4*tx + j] = s[i][j];
        }
        __syncthreads();  // Ps written, K reads done

        // Load V tile: KV[c*128 + d] = V[kbase+c][d] (coalesced)
        for (int idx = tid; idx < 2048; idx += 256) {
            const int r = idx >> 5, c4 = (idx & 31) << 2;
            *(float4*)&KV[r*128 + c4] =
                *(const float4*)(Vg + (size_t)(kbase + r)*HDc + c4);
        }
        __syncthreads();

        // O += P V  (4 rows x 8 cols per thread)
#pragma unroll 2
        for (int kk = 0; kk < 64; kk++) {
            const float4 va = *(const float4*)&KV[kk*128 + 8*tx];
            const float4 vb = *(const float4*)&KV[kk*128 + 8*tx + 4];
            const float p0 = Ps[(4*ty+0)*68 + kk];
            const float p1 = Ps[(4*ty+1)*68 + kk];
            const float p2 = Ps[(4*ty+2)*68 + kk];
            const float p3 = Ps[(4*ty+3)*68 + kk];
            o[0][0] += p0*va.x; o[0][1] += p0*va.y; o[0][2] += p0*va.z; o[0][3] += p0*va.w;
            o[0][4] += p0*vb.x; o[0][5] += p0*vb.y; o[0][6] += p0*vb.z; o[0][7] += p0*vb.w;
            o[1][0] += p1*va.x; o[1][1] += p1*va.y; o[1][2] += p1*va.z; o[1][3] += p1*va.w;
            o[1][4] += p1*vb.x; o[1][5] += p1*vb.y; o[1][6] += p1*vb.z; o[1][7] += p1*vb.w;
            o[2][0] += p2*va.x; o[2][1] += p2*va.y; o[2][2] += p2*va.z; o[2][3] += p2*va.w;
            o[2][4] += p2*vb.x; o[2][5] += p2*vb.y; o[2][6] += p2*vb.z; o[2][7] += p2*vb.w;
            o[3][0] += p3*va.x; o[3][1] += p3*va.y; o[3][2] += p3*va.z; o[3][3] += p3*va.w;
            o[3][4] += p3*vb.x; o[3][5] += p3*vb.y; o[3][6] += p3*vb.z; o[3][7] += p3*vb.w;
        }
    }

    // Epilogue: normalize and write ctx
#pragma unroll
    for (int i = 0; i < 4; i++) {
        const float inv = 1.f / l_i[i];
        const int r = qbase + 4*ty + i;
        float4 oa, ob;
        oa.x = o[i][0]*inv; oa.y = o[i][1]*inv; oa.z = o[i][2]*inv; oa.w = o[i][3]*inv;
        ob.x = o[i][4]*inv; ob.y = o[i][5]*inv; ob.z = o[i][6]*inv; ob.w = o[i][7]*inv;
        *(float4*)(Og + (size_t)r*HDc + 8*tx)     = oa;
        *(float4*)(Og + (size_t)r*HDc + 8*tx + 4) = ob;
    }
}

// ---------------------------------------------------------------------------
extern "C" void kernel_launch(void* const* d_in, const int* in_sizes, int n_in,
                              void* d_out, int out_size)
{
    const float* x  = (const float*)d_in[0];
    const float* y  = (const float*)d_in[1];
    const float* Wq = (const float*)d_in[2];
    const float* bq = (const float*)d_in[3];
    const float* Wk = (const float*)d_in[4];
    const float* bk = (const float*)d_in[5];
    const float* Wv = (const float*)d_in[6];
    const float* bv = (const float*)d_in[7];
    const float* Wo = (const float*)d_in[8];
    const float* bo = (const float*)d_in[9];
    float* out = (float*)d_out;

    static bool attr_set = false;
    // setting an attribute is idempotent and capture-safe; do it every call
    cudaFuncSetAttribute(flash_attn,
                         cudaFuncAttributeMaxDynamicSharedMemorySize,
                         FLASH_SMEM);
    (void)attr_set;

    dim3 gblk(256);
    dim3 ggrid(Dc/128, Mc/128);   // (8, 64)

    gemm_abt<0,0><<<ggrid, gblk>>>(x, Wq, bq, nullptr);  // Q
    gemm_abt<0,1><<<ggrid, gblk>>>(y, Wk, bk, nullptr);  // K
    gemm_abt<0,2><<<ggrid, gblk>>>(y, Wv, bv, nullptr);  // V

    dim3 fgrid(Tc/64, Bc*Hc);     // (32, 32)
    flash_attn<<<fgrid, gblk, FLASH_SMEM>>>();

    gemm_abt<1,0><<<ggrid, gblk>>>(nullptr, Wo, bo, out); // out projection
}

// round 3
// speedup vs baseline: 3.3241x; 3.3241x over previous
#include <cuda_runtime.h>
#include <math.h>
#include <stdint.h>

#define Bc  4
#define Tc  2048
#define Dc  1024
#define Hc  8
#define HDc 128
#define Mc  (Bc*Tc)

// Scratch (tf32-rounded fp32 values)
__device__ float g_q[Bc*Tc*Dc];
__device__ float g_k[Bc*Tc*Dc];
__device__ float g_v[Bc*Tc*Dc];
__device__ float g_ctx[Bc*Tc*Dc];
__device__ float g_x[Bc*Tc*Dc];
__device__ float g_y[Bc*Tc*Dc];
__device__ float g_w[4][Dc*Dc];

// ---------------------------------------------------------------------------
// helpers
// ---------------------------------------------------------------------------
__device__ __forceinline__ uint32_t smem_u32(const void* p) {
    uint32_t a;
    asm("{ .reg .u64 t; cvta.to.shared.u64 t, %1; cvt.u32.u64 %0, t; }"
        : "=r"(a) : "l"(p));
    return a;
}
__device__ __forceinline__ float rn_tf32(float x) {
    uint32_t r;
    asm("cvt.rna.tf32.f32 %0, %1;" : "=r"(r) : "f"(x));
    return __uint_as_float(r);
}
__device__ __forceinline__ float ex2(float x) {
    float y;
    asm("ex2.approx.f32 %0, %1;" : "=f"(y) : "f"(x));
    return y;
}
__device__ __forceinline__ void cp16(uint32_t dst, const void* src) {
    asm volatile("cp.async.cg.shared.global [%0], [%1], 16;" :: "r"(dst), "l"(src));
}
#define CP_COMMIT() asm volatile("cp.async.commit_group;" ::: "memory")
#define CP_WAIT1()  asm volatile("cp.async.wait_group 1;" ::: "memory")
#define CP_WAIT0()  asm volatile("cp.async.wait_group 0;" ::: "memory")

// m16n8k8 tf32 warp MMA, D accumulates in place.
// Fragments (lane = g*4+t, g=lane>>2, t=lane&3):
//  A(16x8): a0=(g,t) a1=(g+8,t) a2=(g,t+4) a3=(g+8,t+4)
//  B(8x8):  b0=(k=t,n=g) b1=(k=t+4,n=g)
//  C(16x8): c0=(g,2t) c1=(g,2t+1) c2=(g+8,2t) c3=(g+8,2t+1)
__device__ __forceinline__ void mma8(float* d, const float* a, float b0, float b1) {
    asm volatile(
        "mma.sync.aligned.m16n8k8.row.col.f32.tf32.tf32.f32 "
        "{%0,%1,%2,%3}, {%4,%5,%6,%7}, {%8,%9}, {%0,%1,%2,%3};"
        : "+f"(d[0]), "+f"(d[1]), "+f"(d[2]), "+f"(d[3])
        : "r"(__float_as_uint(a[0])), "r"(__float_as_uint(a[1])),
          "r"(__float_as_uint(a[2])), "r"(__float_as_uint(a[3])),
          "r"(__float_as_uint(b0)),   "r"(__float_as_uint(b1)));
}

// ---------------------------------------------------------------------------
// RN-convert fp32 -> tf32-rounded fp32
// ---------------------------------------------------------------------------
__global__ void conv_tf32(const float4* __restrict__ in, float4* __restrict__ out,
                          int n4) {
    int i = blockIdx.x * blockDim.x + threadIdx.x;
    if (i < n4) {
        float4 v = in[i];
        v.x = rn_tf32(v.x); v.y = rn_tf32(v.y);
        v.z = rn_tf32(v.z); v.w = rn_tf32(v.w);
        out[i] = v;
    }
}

// ---------------------------------------------------------------------------
// tf32 warp-MMA GEMM: out[m,n] = sum_k A[m,k]*W[n,k] + bias[n]
// 128x128 CTA tile, 8 warps (warp tile 32x64), K-chunk 32, double buffer.
// MODE 0: A plain [M,K]; output head layout (SEL 0=q,1=k,2=v), tf32-rounded
// MODE 1: A gathered from g_ctx head layout; output plain [M,N] fp32
// smem: A0[128][36] A1 B0[128][36] B1 = 4*18432 = 73728 B
// ---------------------------------------------------------------------------
#define GEMM_SMEM 73728

template<int MODE, int SEL>
__global__ __launch_bounds__(256, 1)
void gemm_tc(const float* __restrict__ Ain, const float* __restrict__ Wg,
             const float* __restrict__ bias, float* __restrict__ outp)
{
    extern __shared__ __align__(16) char smem[];
    float* AS0 = (float*)smem;
    float* AS1 = (float*)(smem + 18432);
    float* BS0 = (float*)(smem + 36864);
    float* BS1 = (float*)(smem + 55296);

    const int tid = threadIdx.x;
    const int wid = tid >> 5, lane = tid & 31;
    const int g = lane >> 2, t = lane & 3;
    const int wm = (wid & 3) * 32, wn = (wid >> 2) * 64;
    const int bn = blockIdx.x * 128, bm = blockIdx.y * 128;

    const float* A = (MODE == 0) ? Ain : (const float*)g_ctx;
    float* out = (MODE == 0) ? (SEL == 0 ? g_q : (SEL == 1 ? g_k : g_v)) : outp;

    auto issue = [&](float* dA, float* dB, int k0) {
        const uint32_t da = smem_u32(dA);
        const uint32_t db = smem_u32(dB);
#pragma unroll
        for (int it = 0; it < 4; it++) {
            const int idx = tid + it * 256;          // 0..1023
            const int row = idx >> 3, s = idx & 7;
            const float* src;
            if (MODE == 0) {
                src = A + (size_t)(bm + row) * Dc + k0 + s * 4;
            } else {
                const int m = bm + row, b = m >> 11, tt = m & 2047;
                const int kg = k0 + s * 4;
                const int h = kg >> 7, d = kg & 127;
                src = A + (((size_t)(b * Hc + h) * Tc + tt) * HDc + d);
            }
            cp16(da + (uint32_t)(row * 36 + s * 4) * 4u, src);
        }
#pragma unroll
        for (int it = 0; it < 4; it++) {
            const int idx = tid + it * 256;
            const int row = idx >> 3, s = idx & 7;
            cp16(db + (uint32_t)(row * 36 + s * 4) * 4u,
                 Wg + (size_t)(bn + row) * Dc + k0 + s * 4);
        }
        CP_COMMIT();
    };

    float c[2][8][4];
#pragma unroll
    for (int mt = 0; mt < 2; mt++)
#pragma unroll
        for (int nt = 0; nt < 8; nt++)
#pragma unroll
            for (int j = 0; j < 4; j++) c[mt][nt][j] = 0.f;

    issue(AS0, BS0, 0);
    issue(AS1, BS1, 32);

    for (int i = 0; i < 32; i++) {
        if (i == 31) { CP_WAIT0(); } else { CP_WAIT1(); }
        __syncthreads();

        const float* As = (i & 1) ? AS1 : AS0;
        const float* Bs = (i & 1) ? BS1 : BS0;

#pragma unroll
        for (int ks = 0; ks < 4; ks++) {
            const int kk = ks * 8;
            float a[2][4];
#pragma unroll
            for (int mt = 0; mt < 2; mt++) {
                const float* ap = As + (wm + mt * 16 + g) * 36 + kk + t;
                a[mt][0] = ap[0];
                a[mt][1] = ap[8 * 36];
                a[mt][2] = ap[4];
                a[mt][3] = ap[8 * 36 + 4];
            }
#pragma unroll
            for (int nt = 0; nt < 8; nt++) {
                const float* bp = Bs + (wn + nt * 8 + g) * 36 + kk + t;
                const float b0 = bp[0], b1 = bp[4];
                mma8(c[0][nt], a[0], b0, b1);
                mma8(c[1][nt], a[1], b0, b1);
            }
        }
        __syncthreads();
        if (i + 2 < 32) issue((i & 1) ? AS1 : AS0, (i & 1) ? BS1 : BS0,
                              (i + 2) * 32);
    }

    // Epilogue: fragments -> global (float2), + bias
#pragma unroll
    for (int mt = 0; mt < 2; mt++) {
        const int r0 = bm + wm + mt * 16 + g;
        const int r1 = r0 + 8;
#pragma unroll
        for (int nt = 0; nt < 8; nt++) {
            const int cl = wn + nt * 8 + 2 * t;     // local col, < 128
            const int col = bn + cl;
            const float bx = __ldg(bias + col), by = __ldg(bias + col + 1);
            float v00 = c[mt][nt][0] + bx, v01 = c[mt][nt][1] + by;
            float v10 = c[mt][nt][2] + bx, v11 = c[mt][nt][3] + by;
            if (MODE == 0) {
                v00 = rn_tf32(v00); v01 = rn_tf32(v01);
                v10 = rn_tf32(v10); v11 = rn_tf32(v11);
                const int h = bn >> 7;
                const int b0i = r0 >> 11, t0i = r0 & 2047;
                const int b1i = r1 >> 11, t1i = r1 & 2047;
                *(float2*)&out[(((size_t)(b0i * Hc + h) * Tc + t0i) * HDc) + cl]
                    = make_float2(v00, v01);
                *(float2*)&out[(((size_t)(b1i * Hc + h) * Tc + t1i) * HDc) + cl]
                    = make_float2(v10, v11);
            } else {
                *(float2*)&out[(size_t)r0 * Dc + col] = make_float2(v00, v01);
                *(float2*)&out[(size_t)r1 * Dc + col] = make_float2(v10, v11);
            }
        }
    }
}

// ---------------------------------------------------------------------------
// Flash attention, tf32 warp MMA, causal.
// Block: 256 threads (8 warps). Q tile 128 rows (warp: 16 rows), K tile 64.
// Q fragments in registers; K/V double-buffered in smem (stride 132);
// P via per-warp-private smem (stride 68). exp2-domain softmax.
// smem: K0,K1,V0,V1 (64*132*4 = 33792 each) + Ps[128][68] = 169984 B
// ---------------------------------------------------------------------------
#define FLASH_SMEM (4*33792 + 128*68*4)

__global__ __launch_bounds__(256, 1)
void flash_attn()
{
    extern __shared__ __align__(16) char smem[];
    float* KS0 = (float*)smem;
    float* KS1 = (float*)(smem + 33792);
    float* VS0 = (float*)(smem + 67584);
    float* VS1 = (float*)(smem + 101376);
    float* Ps  = (float*)(smem + 135168);

    const int bh  = blockIdx.y;
    const int qt  = blockIdx.x;
    const int qb  = qt * 128;
    const int tid = threadIdx.x;
    const int wid = tid >> 5, lane = tid & 31;
    const int g = lane >> 2, t = lane & 3;
    const int wq = wid * 16;

    const float* Qg = g_q + (size_t)bh * Tc * HDc;
    const float* Kg = g_k + (size_t)bh * Tc * HDc;
    const float* Vg = g_v + (size_t)bh * Tc * HDc;
    float*       Og = g_ctx + (size_t)bh * Tc * HDc;

    // Q fragments (held for the whole loop)
    float qf[16][4];
    {
        const int r0 = qb + wq + g, r1 = r0 + 8;
#pragma unroll
        for (int ds = 0; ds < 16; ds++) {
            qf[ds][0] = Qg[(size_t)r0 * HDc + ds * 8 + t];
            qf[ds][1] = Qg[(size_t)r1 * HDc + ds * 8 + t];
            qf[ds][2] = Qg[(size_t)r0 * HDc + ds * 8 + t + 4];
            qf[ds][3] = Qg[(size_t)r1 * HDc + ds * 8 + t + 4];
        }
    }

    float o[16][4];
#pragma unroll
    for (int nt = 0; nt < 16; nt++)
#pragma unroll
        for (int j = 0; j < 4; j++) o[nt][j] = 0.f;

    float m0 = -1e30f, m1 = -1e30f, l0 = 0.f, l1 = 0.f;
    const int ktmax = 2 * qt + 1;

    auto issue_kv = [&](float* Kd, float* Vd, int kt) {
        const int kb = kt * 64;
        const uint32_t kd = smem_u32(Kd);
        const uint32_t vd = smem_u32(Vd);
#pragma unroll
        for (int it = 0; it < 8; it++) {
            const int idx = tid + it * 256;        // 0..2047
            const int c = idx >> 5, s = idx & 31;
            cp16(kd + (uint32_t)(c * 132 + s * 4) * 4u,
                 Kg + (size_t)(kb + c) * HDc + s * 4);
        }
#pragma unroll
        for (int it = 0; it < 8; it++) {
            const int idx = tid + it * 256;
            const int c = idx >> 5, s = idx & 31;
            cp16(vd + (uint32_t)(c * 132 + s * 4) * 4u,
                 Vg + (size_t)(kb + c) * HDc + s * 4);
        }
        CP_COMMIT();
    };

    issue_kv(KS0, VS0, 0);

    const float Csc = 0.12751743342f;   // (1/sqrt(128)) * log2(e)

    for (int kt = 0; kt <= ktmax; kt++) {
        const int cur = kt & 1;
        if (kt < ktmax) {
            issue_kv(cur ? KS0 : KS1, cur ? VS0 : VS1, kt + 1);
            CP_WAIT1();
        } else {
            CP_WAIT0();
        }
        __syncthreads();

        const float* Ks = cur ? KS1 : KS0;
        const float* Vs = cur ? VS1 : VS0;
        const int kb = kt * 64;

        // S = Q K^T   (warp: 16 q-rows x 64 k-cols)
        float s[8][4];
#pragma unroll
        for (int nt = 0; nt < 8; nt++)
#pragma unroll
            for (int j = 0; j < 4; j++) s[nt][j] = 0.f;

#pragma unroll
        for (int ds = 0; ds < 16; ds++) {
#pragma unroll
            for (int nt = 0; nt < 8; nt++) {
                const float* bp = Ks + (nt * 8 + g) * 132 + ds * 8 + t;
                mma8(s[nt], qf[ds], bp[0], bp[4]);
            }
        }

        // scale (log2 domain) + causal mask
        const int qr0 = qb + wq + g, qr1 = qr0 + 8;
        const bool needm = (kt >= 2 * qt);
#pragma unroll
        for (int nt = 0; nt < 8; nt++) {
            const int c0 = kb + nt * 8 + 2 * t;
            float v0 = s[nt][0] * Csc, v1 = s[nt][1] * Csc;
            float v2 = s[nt][2] * Csc, v3 = s[nt][3] * Csc;
            if (needm) {
                if (c0     > qr0) v0 = -1e30f;
                if (c0 + 1 > qr0) v1 = -1e30f;
                if (c0     > qr1) v2 = -1e30f;
                if (c0 + 1 > qr1) v3 = -1e30f;
            }
            s[nt][0] = v0; s[nt][1] = v1; s[nt][2] = v2; s[nt][3] = v3;
        }

        // row max (quad shuffle: lanes sharing g hold the full row)
        float mx0 = -1e30f, mx1 = -1e30f;
#pragma unroll
        for (int nt = 0; nt < 8; nt++) {
            mx0 = fmaxf(mx0, fmaxf(s[nt][0], s[nt][1]));
            mx1 = fmaxf(mx1, fmaxf(s[nt][2], s[nt][3]));
        }
        mx0 = fmaxf(mx0, __shfl_xor_sync(0xffffffffu, mx0, 1));
        mx0 = fmaxf(mx0, __shfl_xor_sync(0xffffffffu, mx0, 2));
        mx1 = fmaxf(mx1, __shfl_xor_sync(0xffffffffu, mx1, 1));
        mx1 = fmaxf(mx1, __shfl_xor_sync(0xffffffffu, mx1, 2));

        const float mn0 = fmaxf(m0, mx0), mn1 = fmaxf(m1, mx1);
        const float a0 = ex2(m0 - mn0), a1 = ex2(m1 - mn1);

        float ls0 = 0.f, ls1 = 0.f;
#pragma unroll
        for (int nt = 0; nt < 8; nt++) {
            const float p0 = ex2(s[nt][0] - mn0);
            const float p1 = ex2(s[nt][1] - mn0);
            const float p2 = ex2(s[nt][2] - mn1);
            const float p3 = ex2(s[nt][3] - mn1);
            ls0 += p0 + p1; ls1 += p2 + p3;
            *(float2*)&Ps[(wq + g) * 68 + nt * 8 + 2 * t]
                = make_float2(rn_tf32(p0), rn_tf32(p1));
            *(float2*)&Ps[(wq + g + 8) * 68 + nt * 8 + 2 * t]
                = make_float2(rn_tf32(p2), rn_tf32(p3));
        }
        ls0 += __shfl_xor_sync(0xffffffffu, ls0, 1);
        ls0 += __shfl_xor_sync(0xffffffffu, ls0, 2);
        ls1 += __shfl_xor_sync(0xffffffffu, ls1, 1);
        ls1 += __shfl_xor_sync(0xffffffffu, ls1, 2);
        l0 = l0 * a0 + ls0;
        l1 = l1 * a1 + ls1;
        m0 = mn0; m1 = mn1;

        // rescale O
#pragma unroll
        for (int nt = 0; nt < 16; nt++) {
            o[nt][0] *= a0; o[nt][1] *= a0;
            o[nt][2] *= a1; o[nt][3] *= a1;
        }
        __syncwarp();

        // O += P V   (warp: 16 q-rows x 128 d-cols)
#pragma unroll
        for (int ks = 0; ks < 8; ks++) {
            float pa[4];
            pa[0] = Ps[(wq + g) * 68 + ks * 8 + t];
            pa[1] = Ps[(wq + g + 8) * 68 + ks * 8 + t];
            pa[2] = Ps[(wq + g) * 68 + ks * 8 + t + 4];
            pa[3] = Ps[(wq + g + 8) * 68 + ks * 8 + t + 4];
#pragma unroll
            for (int nt = 0; nt < 16; nt++) {
                const float* vp = Vs + (ks * 8 + t) * 132 + nt * 8 + g;
                mma8(o[nt], pa, vp[0], vp[4 * 132]);
            }
        }
        __syncthreads();
    }

    // epilogue: normalize, round to tf32 (feeds output projection), store
    const float il0 = 1.f / l0, il1 = 1.f / l1;
    const int r0 = qb + wq + g, r1 = r0 + 8;
#pragma unroll
    for (int nt = 0; nt < 16; nt++) {
        const int c = nt * 8 + 2 * t;
        *(float2*)&Og[(size_t)r0 * HDc + c] =
            make_float2(rn_tf32(o[nt][0] * il0), rn_tf32(o[nt][1] * il0));
        *(float2*)&Og[(size_t)r1 * HDc + c] =
            make_float2(rn_tf32(o[nt][2] * il1), rn_tf32(o[nt][3] * il1));
    }
}

// ---------------------------------------------------------------------------
extern "C" void kernel_launch(void* const* d_in, const int* in_sizes, int n_in,
                              void* d_out, int out_size)
{
    const float* x  = (const float*)d_in[0];
    const float* y  = (const float*)d_in[1];
    const float* Wq = (const float*)d_in[2];
    const float* bq = (const float*)d_in[3];
    const float* Wk = (const float*)d_in[4];
    const float* bk = (const float*)d_in[5];
    const float* Wv = (const float*)d_in[6];
    const float* bv = (const float*)d_in[7];
    const float* Wo = (const float*)d_in[8];
    const float* bo = (const float*)d_in[9];
    float* out = (float*)d_out;

    cudaFuncSetAttribute(flash_attn,
                         cudaFuncAttributeMaxDynamicSharedMemorySize, FLASH_SMEM);
    cudaFuncSetAttribute(gemm_tc<0,0>,
                         cudaFuncAttributeMaxDynamicSharedMemorySize, GEMM_SMEM);
    cudaFuncSetAttribute(gemm_tc<0,1>,
                         cudaFuncAttributeMaxDynamicSharedMemorySize, GEMM_SMEM);
    cudaFuncSetAttribute(gemm_tc<0,2>,
                         cudaFuncAttributeMaxDynamicSharedMemorySize, GEMM_SMEM);
    cudaFuncSetAttribute(gemm_tc<1,0>,
                         cudaFuncAttributeMaxDynamicSharedMemorySize, GEMM_SMEM);

    // 1. RN-convert operands to tf32
    float* gx; cudaGetSymbolAddress((void**)&gx, g_x);
    float* gy; cudaGetSymbolAddress((void**)&gy, g_y);
    float* gw; cudaGetSymbolAddress((void**)&gw, g_w);
    const int nXY4 = (Mc * Dc) / 4;
    const int nW4  = (Dc * Dc) / 4;
    conv_tf32<<<(nXY4 + 255)/256, 256>>>((const float4*)x,  (float4*)gx, nXY4);
    conv_tf32<<<(nXY4 + 255)/256, 256>>>((const float4*)y,  (float4*)gy, nXY4);
    conv_tf32<<<(nW4  + 255)/256, 256>>>((const float4*)Wq, (float4*)(gw + 0*Dc*Dc), nW4);
    conv_tf32<<<(nW4  + 255)/256, 256>>>((const float4*)Wk, (float4*)(gw + 1*Dc*Dc), nW4);
    conv_tf32<<<(nW4  + 255)/256, 256>>>((const float4*)Wv, (float4*)(gw + 2*Dc*Dc), nW4);
    conv_tf32<<<(nW4  + 255)/256, 256>>>((const float4*)Wo, (float4*)(gw + 3*Dc*Dc), nW4);

    // 2. Projections
    dim3 gblk(256);
    dim3 ggrid(Dc/128, Mc/128);   // (8, 64)
    gemm_tc<0,0><<<ggrid, gblk, GEMM_SMEM>>>(gx, gw + 0*Dc*Dc, bq, nullptr);
    gemm_tc<0,1><<<ggrid, gblk, GEMM_SMEM>>>(gy, gw + 1*Dc*Dc, bk, nullptr);
    gemm_tc<0,2><<<ggrid, gblk, GEMM_SMEM>>>(gy, gw + 2*Dc*Dc, bv, nullptr);

    // 3. Attention
    dim3 fgrid(Tc/128, Bc*Hc);    // (16, 32)
    flash_attn<<<fgrid, gblk, FLASH_SMEM>>>();

    // 4. Output projection
    gemm_tc<1,0><<<ggrid, gblk, GEMM_SMEM>>>(nullptr, gw + 3*Dc*Dc, bo, out);
}

// round 5
// speedup vs baseline: 3.4861x; 1.0488x over previous
#include <cuda_runtime.h>
#include <math.h>
#include <stdint.h>

#define Bc  4
#define Tc  2048
#define Dc  1024
#define Hc  8
#define HDc 128
#define Mc  (Bc*Tc)

// Scratch (tf32-rounded fp32 values)
__device__ float g_q[Bc*Tc*Dc];
__device__ float g_k[Bc*Tc*Dc];
__device__ float g_v[Bc*Tc*Dc];
__device__ float g_ctx[Bc*Tc*Dc];
__device__ float g_x[Bc*Tc*Dc];
__device__ float g_y[Bc*Tc*Dc];
__device__ float g_w[4][Dc*Dc];

// ---------------------------------------------------------------------------
// helpers
// ---------------------------------------------------------------------------
__device__ __forceinline__ uint32_t smem_u32(const void* p) {
    uint32_t a;
    asm("{ .reg .u64 t; cvta.to.shared.u64 t, %1; cvt.u32.u64 %0, t; }"
        : "=r"(a) : "l"(p));
    return a;
}
__device__ __forceinline__ float rn_tf32(float x) {
    uint32_t r;
    asm("cvt.rna.tf32.f32 %0, %1;" : "=r"(r) : "f"(x));
    return __uint_as_float(r);
}
__device__ __forceinline__ float ex2(float x) {
    float y;
    asm("ex2.approx.f32 %0, %1;" : "=f"(y) : "f"(x));
    return y;
}
__device__ __forceinline__ void cp16(uint32_t dst, const void* src) {
    asm volatile("cp.async.cg.shared.global [%0], [%1], 16;" :: "r"(dst), "l"(src));
}
#define CP_COMMIT() asm volatile("cp.async.commit_group;" ::: "memory")
#define CP_WAIT2()  asm volatile("cp.async.wait_group 2;" ::: "memory")
#define CP_WAIT1()  asm volatile("cp.async.wait_group 1;" ::: "memory")
#define CP_WAIT0()  asm volatile("cp.async.wait_group 0;" ::: "memory")

// ldmatrix x4: four 8x4-float blocks (b16 view). Lane L: row = base+(L&15),
// col = base_col + ((L>>4)&1)*4.
__device__ __forceinline__ void ldm4(uint32_t addr, uint32_t* r) {
    asm volatile("ldmatrix.sync.aligned.m8n8.x4.shared.b16 {%0,%1,%2,%3}, [%4];"
                 : "=r"(r[0]), "=r"(r[1]), "=r"(r[2]), "=r"(r[3]) : "r"(addr));
}

// m16n8k8 tf32 warp MMA, accumulate in place (uint fragments).
__device__ __forceinline__ void mma8u(float* d, const uint32_t* a,
                                      uint32_t b0, uint32_t b1) {
    asm volatile(
        "mma.sync.aligned.m16n8k8.row.col.f32.tf32.tf32.f32 "
        "{%0,%1,%2,%3}, {%4,%5,%6,%7}, {%8,%9}, {%0,%1,%2,%3};"
        : "+f"(d[0]), "+f"(d[1]), "+f"(d[2]), "+f"(d[3])
        : "r"(a[0]), "r"(a[1]), "r"(a[2]), "r"(a[3]), "r"(b0), "r"(b1));
}

// m16n8k8 tf32 warp MMA, float fragments (round-3 proven path).
__device__ __forceinline__ void mma8(float* d, const float* a, float b0, float b1) {
    asm volatile(
        "mma.sync.aligned.m16n8k8.row.col.f32.tf32.tf32.f32 "
        "{%0,%1,%2,%3}, {%4,%5,%6,%7}, {%8,%9}, {%0,%1,%2,%3};"
        : "+f"(d[0]), "+f"(d[1]), "+f"(d[2]), "+f"(d[3])
        : "r"(__float_as_uint(a[0])), "r"(__float_as_uint(a[1])),
          "r"(__float_as_uint(a[2])), "r"(__float_as_uint(a[3])),
          "r"(__float_as_uint(b0)),   "r"(__float_as_uint(b1)));
}

// ---------------------------------------------------------------------------
// RN-convert fp32 -> tf32-rounded fp32
// ---------------------------------------------------------------------------
__global__ void conv_tf32(const float4* __restrict__ in, float4* __restrict__ out,
                          int n4) {
    int i = blockIdx.x * blockDim.x + threadIdx.x;
    if (i < n4) {
        float4 v = in[i];
        v.x = rn_tf32(v.x); v.y = rn_tf32(v.y);
        v.z = rn_tf32(v.z); v.w = rn_tf32(v.w);
        out[i] = v;
    }
}

// ---------------------------------------------------------------------------
// tf32 warp-MMA GEMM v2 (UNCHANGED from round 4 — bisect subject):
// CTA tile 256x128, 8 warps (warp tile 64x64), K-chunk 32, 3-stage cp.async,
// ldmatrix fragment loads.
// ---------------------------------------------------------------------------
#define GEMM_SMEM 165888
#define GSTG 13824          // stage stride in floats

template<int MODE, int SEL>
__global__ __launch_bounds__(256, 1)
void gemm_tc(const float* __restrict__ Ain, const float* __restrict__ Wg,
             const float* __restrict__ bias, float* __restrict__ outp)
{
    extern __shared__ __align__(16) float smem[];
    const uint32_t sb = smem_u32(smem);

    const int tid = threadIdx.x;
    const int wid = tid >> 5, lane = tid & 31;
    const int g = lane >> 2, t = lane & 3;
    const int lrow = lane & 15, lch = (lane >> 4) & 1;
    const int wm = (wid & 3) * 64, wn = (wid >> 2) * 64;
    const int bn = blockIdx.x * 128, bm = blockIdx.y * 256;

    const float* A = (MODE == 0) ? Ain : (const float*)g_ctx;
    float* out = (MODE == 0) ? (SEL == 0 ? g_q : (SEL == 1 ? g_k : g_v)) : outp;

    auto issue = [&](int stg, int k0) {
        const uint32_t da = sb + (uint32_t)(stg * GSTG) * 4u;
        const uint32_t db = da + 9216u * 4u;
#pragma unroll
        for (int it = 0; it < 8; it++) {
            const int idx = tid + it * 256;
            const int row = idx >> 3, s = idx & 7;
            const float* src;
            if (MODE == 0) {
                src = A + (size_t)(bm + row) * Dc + k0 + s * 4;
            } else {
                const int m = bm + row, b = m >> 11, tt = m & 2047;
                const int kg = k0 + s * 4;
                const int h = kg >> 7, d = kg & 127;
                src = A + (((size_t)(b * Hc + h) * Tc + tt) * HDc + d);
            }
            cp16(da + (uint32_t)(row * 36 + s * 4) * 4u, src);
        }
#pragma unroll
        for (int it = 0; it < 4; it++) {
            const int idx = tid + it * 256;
            const int row = idx >> 3, s = idx & 7;
            cp16(db + (uint32_t)(row * 36 + s * 4) * 4u,
                 Wg + (size_t)(bn + row) * Dc + k0 + s * 4);
        }
        CP_COMMIT();
    };

    float c[4][8][4];
#pragma unroll
    for (int mt = 0; mt < 4; mt++)
#pragma unroll
        for (int nt = 0; nt < 8; nt++)
#pragma unroll
            for (int j = 0; j < 4; j++) c[mt][nt][j] = 0.f;

    issue(0, 0); issue(1, 32); issue(2, 64);

    for (int i = 0; i < 32; i++) {
        if (i < 30)      { CP_WAIT2(); }
        else if (i == 30){ CP_WAIT1(); }
        else             { CP_WAIT0(); }
        __syncthreads();

        const uint32_t as = sb + (uint32_t)((i % 3) * GSTG) * 4u;
        const uint32_t bs = as + 9216u * 4u;

#pragma unroll
        for (int ks = 0; ks < 4; ks++) {
            const int col = ks * 8 + lch * 4;
            uint32_t a[4][4], br[4][4];
#pragma unroll
            for (int mt = 0; mt < 4; mt++)
                ldm4(as + (uint32_t)((wm + mt * 16 + lrow) * 36 + col) * 4u,
                     a[mt]);
#pragma unroll
            for (int p = 0; p < 4; p++)
                ldm4(bs + (uint32_t)((wn + p * 16 + lrow) * 36 + col) * 4u,
                     br[p]);
#pragma unroll
            for (int mt = 0; mt < 4; mt++)
#pragma unroll
                for (int p = 0; p < 4; p++) {
                    mma8u(c[mt][2 * p],     a[mt], br[p][0], br[p][2]);
                    mma8u(c[mt][2 * p + 1], a[mt], br[p][1], br[p][3]);
                }
        }
        __syncthreads();
        if (i + 3 < 32) issue((i + 3) % 3, (i + 3) * 32);
    }

#pragma unroll
    for (int mt = 0; mt < 4; mt++) {
        const int r0 = bm + wm + mt * 16 + g;
        const int r1 = r0 + 8;
#pragma unroll
        for (int nt = 0; nt < 8; nt++) {
            const int cl = wn + nt * 8 + 2 * t;
            const int col = bn + cl;
            const float bx = __ldg(bias + col), by = __ldg(bias + col + 1);
            float v00 = c[mt][nt][0] + bx, v01 = c[mt][nt][1] + by;
            float v10 = c[mt][nt][2] + bx, v11 = c[mt][nt][3] + by;
            if (MODE == 0) {
                v00 = rn_tf32(v00); v01 = rn_tf32(v01);
                v10 = rn_tf32(v10); v11 = rn_tf32(v11);
                const int h = bn >> 7;
                const int b0i = r0 >> 11, t0i = r0 & 2047;
                const int b1i = r1 >> 11, t1i = r1 & 2047;
                *(float2*)&out[(((size_t)(b0i * Hc + h) * Tc + t0i) * HDc) + cl]
                    = make_float2(v00, v01);
                *(float2*)&out[(((size_t)(b1i * Hc + h) * Tc + t1i) * HDc) + cl]
                    = make_float2(v10, v11);
            } else {
                *(float2*)&out[(size_t)r0 * Dc + col] = make_float2(v00, v01);
                *(float2*)&out[(size_t)r1 * Dc + col] = make_float2(v10, v11);
            }
        }
    }
}

// ---------------------------------------------------------------------------
// Flash attention — ROUND-3 VERSION VERBATIM (known good).
// 256 threads / 8 warps, Q tile 128 (warp 16 rows), K tile 64,
// Q fragments in registers, scalar LDS fragments, exp2-domain softmax.
// ---------------------------------------------------------------------------
#define FLASH_SMEM (4*33792 + 128*68*4)

__global__ __launch_bounds__(256, 1)
void flash_attn()
{
    extern __shared__ __align__(16) char fsm[];
    float* KS0 = (float*)fsm;
    float* KS1 = (float*)(fsm + 33792);
    float* VS0 = (float*)(fsm + 67584);
    float* VS1 = (float*)(fsm + 101376);
    float* Ps  = (float*)(fsm + 135168);

    const int bh  = blockIdx.y;
    const int qt  = blockIdx.x;
    const int qb  = qt * 128;
    const int tid = threadIdx.x;
    const int wid = tid >> 5, lane = tid & 31;
    const int g = lane >> 2, t = lane & 3;
    const int wq = wid * 16;

    const float* Qg = g_q + (size_t)bh * Tc * HDc;
    const float* Kg = g_k + (size_t)bh * Tc * HDc;
    const float* Vg = g_v + (size_t)bh * Tc * HDc;
    float*       Og = g_ctx + (size_t)bh * Tc * HDc;

    // Q fragments (held for the whole loop)
    float qf[16][4];
    {
        const int r0 = qb + wq + g, r1 = r0 + 8;
#pragma unroll
        for (int ds = 0; ds < 16; ds++) {
            qf[ds][0] = Qg[(size_t)r0 * HDc + ds * 8 + t];
            qf[ds][1] = Qg[(size_t)r1 * HDc + ds * 8 + t];
            qf[ds][2] = Qg[(size_t)r0 * HDc + ds * 8 + t + 4];
            qf[ds][3] = Qg[(size_t)r1 * HDc + ds * 8 + t + 4];
        }
    }

    float o[16][4];
#pragma unroll
    for (int nt = 0; nt < 16; nt++)
#pragma unroll
        for (int j = 0; j < 4; j++) o[nt][j] = 0.f;

    float m0 = -1e30f, m1 = -1e30f, l0 = 0.f, l1 = 0.f;
    const int ktmax = 2 * qt + 1;

    auto issue_kv = [&](float* Kd, float* Vd, int kt) {
        const int kb = kt * 64;
        const uint32_t kd = smem_u32(Kd);
        const uint32_t vd = smem_u32(Vd);
#pragma unroll
        for (int it = 0; it < 8; it++) {
            const int idx = tid + it * 256;
            const int c = idx >> 5, s = idx & 31;
            cp16(kd + (uint32_t)(c * 132 + s * 4) * 4u,
                 Kg + (size_t)(kb + c) * HDc + s * 4);
        }
#pragma unroll
        for (int it = 0; it < 8; it++) {
            const int idx = tid + it * 256;
            const int c = idx >> 5, s = idx & 31;
            cp16(vd + (uint32_t)(c * 132 + s * 4) * 4u,
                 Vg + (size_t)(kb + c) * HDc + s * 4);
        }
        CP_COMMIT();
    };

    issue_kv(KS0, VS0, 0);

    const float Csc = 0.12751743342f;   // (1/sqrt(128)) * log2(e)

    for (int kt = 0; kt <= ktmax; kt++) {
        const int cur = kt & 1;
        if (kt < ktmax) {
            issue_kv(cur ? KS0 : KS1, cur ? VS0 : VS1, kt + 1);
            CP_WAIT1();
        } else {
            CP_WAIT0();
        }
        __syncthreads();

        const float* Ks = cur ? KS1 : KS0;
        const float* Vs = cur ? VS1 : VS0;
        const int kb = kt * 64;

        float s[8][4];
#pragma unroll
        for (int nt = 0; nt < 8; nt++)
#pragma unroll
            for (int j = 0; j < 4; j++) s[nt][j] = 0.f;

#pragma unroll
        for (int ds = 0; ds < 16; ds++) {
#pragma unroll
            for (int nt = 0; nt < 8; nt++) {
                const float* bp = Ks + (nt * 8 + g) * 132 + ds * 8 + t;
                mma8(s[nt], qf[ds], bp[0], bp[4]);
            }
        }

        const int qr0 = qb + wq + g, qr1 = qr0 + 8;
        const bool needm = (kt >= 2 * qt);
#pragma unroll
        for (int nt = 0; nt < 8; nt++) {
            const int c0 = kb + nt * 8 + 2 * t;
            float v0 = s[nt][0] * Csc, v1 = s[nt][1] * Csc;
            float v2 = s[nt][2] * Csc, v3 = s[nt][3] * Csc;
            if (needm) {
                if (c0     > qr0) v0 = -1e30f;
                if (c0 + 1 > qr0) v1 = -1e30f;
                if (c0     > qr1) v2 = -1e30f;
                if (c0 + 1 > qr1) v3 = -1e30f;
            }
            s[nt][0] = v0; s[nt][1] = v1; s[nt][2] = v2; s[nt][3] = v3;
        }

        float mx0 = -1e30f, mx1 = -1e30f;
#pragma unroll
        for (int nt = 0; nt < 8; nt++) {
            mx0 = fmaxf(mx0, fmaxf(s[nt][0], s[nt][1]));
            mx1 = fmaxf(mx1, fmaxf(s[nt][2], s[nt][3]));
        }
        mx0 = fmaxf(mx0, __shfl_xor_sync(0xffffffffu, mx0, 1));
        mx0 = fmaxf(mx0, __shfl_xor_sync(0xffffffffu, mx0, 2));
        mx1 = fmaxf(mx1, __shfl_xor_sync(0xffffffffu, mx1, 1));
        mx1 = fmaxf(mx1, __shfl_xor_sync(0xffffffffu, mx1, 2));

        const float mn0 = fmaxf(m0, mx0), mn1 = fmaxf(m1, mx1);
        const float a0 = ex2(m0 - mn0), a1 = ex2(m1 - mn1);

        float ls0 = 0.f, ls1 = 0.f;
#pragma unroll
        for (int nt = 0; nt < 8; nt++) {
            const float p0 = ex2(s[nt][0] - mn0);
            const float p1 = ex2(s[nt][1] - mn0);
            const float p2 = ex2(s[nt][2] - mn1);
            const float p3 = ex2(s[nt][3] - mn1);
            ls0 += p0 + p1; ls1 += p2 + p3;
            *(float2*)&Ps[(wq + g) * 68 + nt * 8 + 2 * t]
                = make_float2(rn_tf32(p0), rn_tf32(p1));
            *(float2*)&Ps[(wq + g + 8) * 68 + nt * 8 + 2 * t]
                = make_float2(rn_tf32(p2), rn_tf32(p3));
        }
        ls0 += __shfl_xor_sync(0xffffffffu, ls0, 1);
        ls0 += __shfl_xor_sync(0xffffffffu, ls0, 2);
        ls1 += __shfl_xor_sync(0xffffffffu, ls1, 1);
        ls1 += __shfl_xor_sync(0xffffffffu, ls1, 2);
        l0 = l0 * a0 + ls0;
        l1 = l1 * a1 + ls1;
        m0 = mn0; m1 = mn1;

#pragma unroll
        for (int nt = 0; nt < 16; nt++) {
            o[nt][0] *= a0; o[nt][1] *= a0;
            o[nt][2] *= a1; o[nt][3] *= a1;
        }
        __syncwarp();

#pragma unroll
        for (int ks = 0; ks < 8; ks++) {
            float pa[4];
            pa[0] = Ps[(wq + g) * 68 + ks * 8 + t];
            pa[1] = Ps[(wq + g + 8) * 68 + ks * 8 + t];
            pa[2] = Ps[(wq + g) * 68 + ks * 8 + t + 4];
            pa[3] = Ps[(wq + g + 8) * 68 + ks * 8 + t + 4];
#pragma unroll
            for (int nt = 0; nt < 16; nt++) {
                const float* vp = Vs + (ks * 8 + t) * 132 + nt * 8 + g;
                mma8(o[nt], pa, vp[0], vp[4 * 132]);
            }
        }
        __syncthreads();
    }

    const float il0 = 1.f / l0, il1 = 1.f / l1;
    const int r0 = qb + wq + g, r1 = r0 + 8;
#pragma unroll
    for (int nt = 0; nt < 16; nt++) {
        const int c = nt * 8 + 2 * t;
        *(float2*)&Og[(size_t)r0 * HDc + c] =
            make_float2(rn_tf32(o[nt][0] * il0), rn_tf32(o[nt][1] * il0));
        *(float2*)&Og[(size_t)r1 * HDc + c] =
            make_float2(rn_tf32(o[nt][2] * il1), rn_tf32(o[nt][3] * il1));
    }
}

// ---------------------------------------------------------------------------
extern "C" void kernel_launch(void* const* d_in, const int* in_sizes, int n_in,
                              void* d_out, int out_size)
{
    const float* x  = (const float*)d_in[0];
    const float* y  = (const float*)d_in[1];
    const float* Wq = (const float*)d_in[2];
    const float* bq = (const float*)d_in[3];
    const float* Wk = (const float*)d_in[4];
    const float* bk = (const float*)d_in[5];
    const float* Wv = (const float*)d_in[6];
    const float* bv = (const float*)d_in[7];
    const float* Wo = (const float*)d_in[8];
    const float* bo = (const float*)d_in[9];
    float* out = (float*)d_out;

    cudaFuncSetAttribute(flash_attn,
                         cudaFuncAttributeMaxDynamicSharedMemorySize, FLASH_SMEM);
    cudaFuncSetAttribute(gemm_tc<0,0>,
                         cudaFuncAttributeMaxDynamicSharedMemorySize, GEMM_SMEM);
    cudaFuncSetAttribute(gemm_tc<0,1>,
                         cudaFuncAttributeMaxDynamicSharedMemorySize, GEMM_SMEM);
    cudaFuncSetAttribute(gemm_tc<0,2>,
                         cudaFuncAttributeMaxDynamicSharedMemorySize, GEMM_SMEM);
    cudaFuncSetAttribute(gemm_tc<1,0>,
                         cudaFuncAttributeMaxDynamicSharedMemorySize, GEMM_SMEM);

    // 1. RN-convert operands to tf32
    float* gx; cudaGetSymbolAddress((void**)&gx, g_x);
    float* gy; cudaGetSymbolAddress((void**)&gy, g_y);
    float* gw; cudaGetSymbolAddress((void**)&gw, g_w);
    const int nXY4 = (Mc * Dc) / 4;
    const int nW4  = (Dc * Dc) / 4;
    conv_tf32<<<(nXY4 + 255)/256, 256>>>((const float4*)x,  (float4*)gx, nXY4);
    conv_tf32<<<(nXY4 + 255)/256, 256>>>((const float4*)y,  (float4*)gy, nXY4);
    conv_tf32<<<(nW4  + 255)/256, 256>>>((const float4*)Wq, (float4*)(gw + 0*Dc*Dc), nW4);
    conv_tf32<<<(nW4  + 255)/256, 256>>>((const float4*)Wk, (float4*)(gw + 1*Dc*Dc), nW4);
    conv_tf32<<<(nW4  + 255)/256, 256>>>((const float4*)Wv, (float4*)(gw + 2*Dc*Dc), nW4);
    conv_tf32<<<(nW4  + 255)/256, 256>>>((const float4*)Wo, (float4*)(gw + 3*Dc*Dc), nW4);

    // 2. Projections (ldmatrix GEMM v2)
    dim3 gblk(256);
    dim3 ggrid(Dc/128, Mc/256);   // (8, 32)
    gemm_tc<0,0><<<ggrid, gblk, GEMM_SMEM>>>(gx, gw + 0*Dc*Dc, bq, nullptr);
    gemm_tc<0,1><<<ggrid, gblk, GEMM_SMEM>>>(gy, gw + 1*Dc*Dc, bk, nullptr);
    gemm_tc<0,2><<<ggrid, gblk, GEMM_SMEM>>>(gy, gw + 2*Dc*Dc, bv, nullptr);

    // 3. Attention (round-3 flash, known good)
    dim3 fgrid(Tc/128, Bc*Hc);    // (16, 32)
    flash_attn<<<fgrid, gblk, FLASH_SMEM>>>();

    // 4. Output projection
    gemm_tc<1,0><<<ggrid, gblk, GEMM_SMEM>>>(nullptr, gw + 3*Dc*Dc, bo, out);
}

// round 6
// speedup vs baseline: 6.1608x; 1.7672x over previous
#include <cuda_runtime.h>
#include <cuda_fp16.h>
#include <math.h>
#include <stdint.h>

#define Bc  4
#define Tc  2048
#define Dc  1024
#define Hc  8
#define HDc 128
#define Mc  (Bc*Tc)

// Scratch (fp16)
__device__ __half g_qh[Bc*Tc*Dc];           // [B,H,T,HD]
__device__ __half g_kh[Bc*Tc*Dc];           // [B,H,T,HD]
__device__ __half g_vt[Bc*Tc*Dc];           // [B,H,HD,T]  (V transposed)
__device__ __half g_ch[Bc*Tc*Dc];           // ctx [B,H,T,HD]
__device__ __half g_xh[Bc*Tc*Dc];
__device__ __half g_yh[Bc*Tc*Dc];
__device__ __half g_wh[4][Dc*Dc];

// ---------------------------------------------------------------------------
// helpers
// ---------------------------------------------------------------------------
__device__ __forceinline__ uint32_t smem_u32(const void* p) {
    uint32_t a;
    asm("{ .reg .u64 t; cvta.to.shared.u64 t, %1; cvt.u32.u64 %0, t; }"
        : "=r"(a) : "l"(p));
    return a;
}
__device__ __forceinline__ float ex2(float x) {
    float y;
    asm("ex2.approx.f32 %0, %1;" : "=f"(y) : "f"(x));
    return y;
}
__device__ __forceinline__ uint32_t h2u(float a, float b) {
    __half2 h = __floats2half2_rn(a, b);
    return *(uint32_t*)&h;
}
__device__ __forceinline__ void cp16(uint32_t dst, const void* src) {
    asm volatile("cp.async.cg.shared.global [%0], [%1], 16;" :: "r"(dst), "l"(src));
}
#define CP_COMMIT() asm volatile("cp.async.commit_group;" ::: "memory")
#define CP_WAIT2()  asm volatile("cp.async.wait_group 2;" ::: "memory")
#define CP_WAIT1()  asm volatile("cp.async.wait_group 1;" ::: "memory")
#define CP_WAIT0()  asm volatile("cp.async.wait_group 0;" ::: "memory")

// m16n8k16 fp16 MMA, f32 accumulate in place.
// lane = g*4+t (g=lane>>2, t=lane&3)
//  A(16x16): a0={A[g][2t],A[g][2t+1]} a1={A[g+8][2t],..} a2={A[g][2t+8],..}
//            a3={A[g+8][2t+8],..}
//  B(16x8):  b0={B[2t][g],B[2t+1][g]} b1={B[2t+8][g],B[2t+9][g]}
//  C(16x8):  c0=C[g][2t] c1=C[g][2t+1] c2=C[g+8][2t] c3=C[g+8][2t+1]
__device__ __forceinline__ void mma16(float* d, const uint32_t* a,
                                      uint32_t b0, uint32_t b1) {
    asm volatile(
        "mma.sync.aligned.m16n8k16.row.col.f32.f16.f16.f32 "
        "{%0,%1,%2,%3}, {%4,%5,%6,%7}, {%8,%9}, {%0,%1,%2,%3};"
        : "+f"(d[0]), "+f"(d[1]), "+f"(d[2]), "+f"(d[3])
        : "r"(a[0]), "r"(a[1]), "r"(a[2]), "r"(a[3]), "r"(b0), "r"(b1));
}

// ---------------------------------------------------------------------------
// fp32 -> fp16 (RN) convert
// ---------------------------------------------------------------------------
__global__ void conv_h(const float4* __restrict__ in, uint2* __restrict__ out,
                       int n4) {
    int i = blockIdx.x * blockDim.x + threadIdx.x;
    if (i < n4) {
        float4 v = in[i];
        uint2 o;
        o.x = h2u(v.x, v.y);
        o.y = h2u(v.z, v.w);
        out[i] = o;
    }
}

// ---------------------------------------------------------------------------
// fp16 warp-MMA GEMM: out[m,n] = sum_k A[m,k]*W[n,k] + bias[n]
// CTA tile 256x128, 8 warps (warp 64x64), K-chunk 32 halves, 3-stage cp.async.
// MODE 0: A = half [M,K]; out = half head layout [B,H,T,HD]
// MODE 1: A gathered from g_ch head layout; out = float plain [M,N]
// MODE 2: A = half [M,K]; out = half V^T layout [B,H,HD,T] (smem-staged)
// smem stage: A 256x40 halves (20480B) + B 128x40 (10240B) = 30720B; x3
// ---------------------------------------------------------------------------
#define GEMM_SMEM (3*30720)

template<int MODE>
__global__ __launch_bounds__(256, 1)
void gemm_h(const __half* __restrict__ A, const __half* __restrict__ Wg,
            const float* __restrict__ bias, __half* __restrict__ outh,
            float* __restrict__ outf)
{
    extern __shared__ __align__(16) char smemc[];
    const uint32_t sb = smem_u32(smemc);

    const int tid = threadIdx.x;
    const int wid = tid >> 5, lane = tid & 31;
    const int g = lane >> 2, t = lane & 3;
    const int wm = (wid & 3) * 64, wn = (wid >> 2) * 64;
    const int bn = blockIdx.x * 128, bm = blockIdx.y * 256;

    auto issue = [&](int stg, int k0) {
        const uint32_t da = sb + (uint32_t)(stg * 30720);
        const uint32_t db = da + 20480u;
#pragma unroll
        for (int it = 0; it < 4; it++) {
            const int idx = tid + it * 256;          // 0..1023
            const int row = idx >> 2, s = idx & 3;   // s: 8-half chunk
            const __half* src;
            if (MODE == 1) {
                const int m = bm + row, b = m >> 11, tt = m & 2047;
                const int kg = k0 + s * 8;
                const int h = kg >> 7, d = kg & 127;
                src = A + (((size_t)(b * Hc + h) * Tc + tt) * HDc + d);
            } else {
                src = A + (size_t)(bm + row) * Dc + k0 + s * 8;
            }
            cp16(da + (uint32_t)(row * 40 + s * 8) * 2u, src);
        }
#pragma unroll
        for (int it = 0; it < 2; it++) {
            const int idx = tid + it * 256;          // 0..511
            const int row = idx >> 2, s = idx & 3;
            cp16(db + (uint32_t)(row * 40 + s * 8) * 2u,
                 Wg + (size_t)(bn + row) * Dc + k0 + s * 8);
        }
        CP_COMMIT();
    };

    float c[4][8][4];
#pragma unroll
    for (int mt = 0; mt < 4; mt++)
#pragma unroll
        for (int nt = 0; nt < 8; nt++)
#pragma unroll
            for (int j = 0; j < 4; j++) c[mt][nt][j] = 0.f;

    issue(0, 0); issue(1, 32); issue(2, 64);

    for (int i = 0; i < 32; i++) {
        if (i < 30)      { CP_WAIT2(); }
        else if (i == 30){ CP_WAIT1(); }
        else             { CP_WAIT0(); }
        __syncthreads();

        const __half* As = (const __half*)(smemc + (i % 3) * 30720);
        const __half* Bs = As + 10240;

#pragma unroll
        for (int ks = 0; ks < 2; ks++) {
            const int kk = ks * 16;
            uint32_t a[4][4];
#pragma unroll
            for (int mt = 0; mt < 4; mt++) {
                const __half* ap = As + (wm + mt * 16 + g) * 40 + kk + 2 * t;
                a[mt][0] = *(const uint32_t*)(ap);
                a[mt][1] = *(const uint32_t*)(ap + 8 * 40);
                a[mt][2] = *(const uint32_t*)(ap + 8);
                a[mt][3] = *(const uint32_t*)(ap + 8 * 40 + 8);
            }
#pragma unroll
            for (int nt = 0; nt < 8; nt++) {
                const __half* bp = Bs + (wn + nt * 8 + g) * 40 + kk + 2 * t;
                const uint32_t b0 = *(const uint32_t*)(bp);
                const uint32_t b1 = *(const uint32_t*)(bp + 8);
#pragma unroll
                for (int mt = 0; mt < 4; mt++)
                    mma16(c[mt][nt], a[mt], b0, b1);
            }
        }
        __syncthreads();
        if (i + 3 < 32) issue((i + 3) % 3, (i + 3) * 32);
    }

    const int b0i_base = bm >> 11, t0 = bm & 2047;
    const int h = bn >> 7;

    if (MODE == 2) {
        // stage transposed tile [128 n][256 m] in smem, then coalesced copy
        __half* Ts = (__half*)smemc;          // stride 264 halves
#pragma unroll
        for (int mt = 0; mt < 4; mt++) {
            const int r0l = wm + mt * 16 + g, r1l = r0l + 8;
#pragma unroll
            for (int nt = 0; nt < 8; nt++) {
                const int cl = wn + nt * 8 + 2 * t;
                const float bx = __ldg(bias + bn + cl);
                const float by = __ldg(bias + bn + cl + 1);
                Ts[(cl    ) * 264 + r0l] = __float2half_rn(c[mt][nt][0] + bx);
                Ts[(cl + 1) * 264 + r0l] = __float2half_rn(c[mt][nt][1] + by);
                Ts[(cl    ) * 264 + r1l] = __float2half_rn(c[mt][nt][2] + bx);
                Ts[(cl + 1) * 264 + r1l] = __float2half_rn(c[mt][nt][3] + by);
            }
        }
        __syncthreads();
        // copy 128 rows x 256 halves to g_vt[(b*H+h)*HD + d][t]
#pragma unroll
        for (int it = 0; it < 16; it++) {
            const int idx = tid + it * 256;          // 0..4095
            const int row = idx >> 5, s = idx & 31;  // s: 8-half chunk
            const uint4 v = *(const uint4*)&Ts[row * 264 + s * 8];
            *(uint4*)&outh[(((size_t)(b0i_base * Hc + h) * HDc + bn % 128 + row)
                            * Tc) + t0 + s * 8] = v;
        }
        return;
    }

#pragma unroll
    for (int mt = 0; mt < 4; mt++) {
        const int r0 = bm + wm + mt * 16 + g;
        const int r1 = r0 + 8;
#pragma unroll
        for (int nt = 0; nt < 8; nt++) {
            const int cl = wn + nt * 8 + 2 * t;
            const int col = bn + cl;
            const float bx = __ldg(bias + col), by = __ldg(bias + col + 1);
            const float v00 = c[mt][nt][0] + bx, v01 = c[mt][nt][1] + by;
            const float v10 = c[mt][nt][2] + bx, v11 = c[mt][nt][3] + by;
            if (MODE == 0) {
                const int b0i = r0 >> 11, t0i = r0 & 2047;
                const int b1i = r1 >> 11, t1i = r1 & 2047;
                *(uint32_t*)&outh[(((size_t)(b0i * Hc + h) * Tc + t0i) * HDc) + cl]
                    = h2u(v00, v01);
                *(uint32_t*)&outh[(((size_t)(b1i * Hc + h) * Tc + t1i) * HDc) + cl]
                    = h2u(v10, v11);
            } else {
                *(float2*)&outf[(size_t)r0 * Dc + col] = make_float2(v00, v01);
                *(float2*)&outf[(size_t)r1 * Dc + col] = make_float2(v10, v11);
            }
        }
    }
}

// ---------------------------------------------------------------------------
// Flash attention fp16 (structure = proven round-3; fp16 fragments).
// 256 threads / 8 warps; Q tile 128 (warp 16 q-rows), K tile 64.
// Q fragments in regs; K row-major smem; V from g_vt (d-major) smem;
// P staged per-warp in smem halves. exp2-domain online softmax.
// smem halves: K0[64][136] K1 | V0[128][72] V1 | Ps[128][72] = 45056 h = 90112 B
// ---------------------------------------------------------------------------
#define FLASH_SMEM 90112
#define HK0  0
#define HK1  8704
#define HV0  17408
#define HV1  26624
#define HPS  35840

__global__ __launch_bounds__(256)
void flash_attn()
{
    extern __shared__ __align__(16) __half fsm[];
    const uint32_t sb = smem_u32(fsm);

    const int bh  = blockIdx.y;
    const int qt  = blockIdx.x;
    const int qb  = qt * 128;
    const int tid = threadIdx.x;
    const int wid = tid >> 5, lane = tid & 31;
    const int g = lane >> 2, t = lane & 3;
    const int wq = wid * 16;

    const __half* Qg  = g_qh + (size_t)bh * Tc * HDc;
    const __half* Kg  = g_kh + (size_t)bh * Tc * HDc;
    const __half* Vtg = g_vt + (size_t)bh * HDc * Tc;
    __half*       Og  = g_ch + (size_t)bh * Tc * HDc;

    __half* Ps = fsm + HPS;

    // Q fragments, held all loop: qf[ds][0..3] for d-chunk ds (16 d each)
    uint32_t qf[8][4];
    {
        const int r0 = qb + wq + g, r1 = r0 + 8;
#pragma unroll
        for (int ds = 0; ds < 8; ds++) {
            qf[ds][0] = *(const uint32_t*)&Qg[(size_t)r0 * HDc + ds * 16 + 2 * t];
            qf[ds][1] = *(const uint32_t*)&Qg[(size_t)r1 * HDc + ds * 16 + 2 * t];
            qf[ds][2] = *(const uint32_t*)&Qg[(size_t)r0 * HDc + ds * 16 + 8 + 2 * t];
            qf[ds][3] = *(const uint32_t*)&Qg[(size_t)r1 * HDc + ds * 16 + 8 + 2 * t];
        }
    }

    float o[16][4];
#pragma unroll
    for (int nt = 0; nt < 16; nt++)
#pragma unroll
        for (int j = 0; j < 4; j++) o[nt][j] = 0.f;

    float m0 = -1e30f, m1 = -1e30f, l0 = 0.f, l1 = 0.f;
    const int ktmax = 2 * qt + 1;

    auto issue_kv = [&](int buf, int kt) {
        const int kb = kt * 64;
        const uint32_t kd = sb + (buf ? HK1 : HK0) * 2u;
        const uint32_t vd = sb + (buf ? HV1 : HV0) * 2u;
#pragma unroll
        for (int it = 0; it < 4; it++) {
            const int idx = tid + it * 256;          // 0..1023
            const int c = idx >> 4, s = idx & 15;
            cp16(kd + (uint32_t)(c * 136 + s * 8) * 2u,
                 Kg + (size_t)(kb + c) * HDc + s * 8);
        }
#pragma unroll
        for (int it = 0; it < 4; it++) {
            const int idx = tid + it * 256;          // 0..1023
            const int d = idx >> 3, s = idx & 7;
            cp16(vd + (uint32_t)(d * 72 + s * 8) * 2u,
                 Vtg + (size_t)d * Tc + kb + s * 8);
        }
        CP_COMMIT();
    };

    issue_kv(0, 0);

    const float Csc = 0.12751743342f;   // (1/sqrt(128)) * log2(e)

    for (int kt = 0; kt <= ktmax; kt++) {
        const int cur = kt & 1;
        if (kt < ktmax) {
            issue_kv(1 - cur, kt + 1);
            CP_WAIT1();
        } else {
            CP_WAIT0();
        }
        __syncthreads();

        const __half* Ks = fsm + (cur ? HK1 : HK0);
        const __half* Vs = fsm + (cur ? HV1 : HV0);
        const int kb = kt * 64;

        // S = Q K^T : warp 16q x 64c
        float s[8][4];
#pragma unroll
        for (int nt = 0; nt < 8; nt++)
#pragma unroll
            for (int j = 0; j < 4; j++) s[nt][j] = 0.f;

#pragma unroll
        for (int ds = 0; ds < 8; ds++) {
#pragma unroll
            for (int nt = 0; nt < 8; nt++) {
                const __half* bp = Ks + (nt * 8 + g) * 136 + ds * 16 + 2 * t;
                const uint32_t b0 = *(const uint32_t*)(bp);
                const uint32_t b1 = *(const uint32_t*)(bp + 8);
                mma16(s[nt], qf[ds], b0, b1);
            }
        }

        // scale + causal mask
        const int qr0 = qb + wq + g, qr1 = qr0 + 8;
        const bool needm = (kt >= 2 * qt);
#pragma unroll
        for (int nt = 0; nt < 8; nt++) {
            const int c0 = kb + nt * 8 + 2 * t;
            float v0 = s[nt][0] * Csc, v1 = s[nt][1] * Csc;
            float v2 = s[nt][2] * Csc, v3 = s[nt][3] * Csc;
            if (needm) {
                if (c0     > qr0) v0 = -1e30f;
                if (c0 + 1 > qr0) v1 = -1e30f;
                if (c0     > qr1) v2 = -1e30f;
                if (c0 + 1 > qr1) v3 = -1e30f;
            }
            s[nt][0] = v0; s[nt][1] = v1; s[nt][2] = v2; s[nt][3] = v3;
        }

        // online softmax (rows qr0 group / qr1 group)
        float mx0 = -1e30f, mx1 = -1e30f;
#pragma unroll
        for (int nt = 0; nt < 8; nt++) {
            mx0 = fmaxf(mx0, fmaxf(s[nt][0], s[nt][1]));
            mx1 = fmaxf(mx1, fmaxf(s[nt][2], s[nt][3]));
        }
        mx0 = fmaxf(mx0, __shfl_xor_sync(0xffffffffu, mx0, 1));
        mx0 = fmaxf(mx0, __shfl_xor_sync(0xffffffffu, mx0, 2));
        mx1 = fmaxf(mx1, __shfl_xor_sync(0xffffffffu, mx1, 1));
        mx1 = fmaxf(mx1, __shfl_xor_sync(0xffffffffu, mx1, 2));

        const float mn0 = fmaxf(m0, mx0), mn1 = fmaxf(m1, mx1);
        const float a0 = ex2(m0 - mn0), a1 = ex2(m1 - mn1);

        float ls0 = 0.f, ls1 = 0.f;
#pragma unroll
        for (int nt = 0; nt < 8; nt++) {
            const float p0 = ex2(s[nt][0] - mn0);
            const float p1 = ex2(s[nt][1] - mn0);
            const float p2 = ex2(s[nt][2] - mn1);
            const float p3 = ex2(s[nt][3] - mn1);
            ls0 += p0 + p1; ls1 += p2 + p3;
            *(uint32_t*)&Ps[(wq + g) * 72 + nt * 8 + 2 * t]     = h2u(p0, p1);
            *(uint32_t*)&Ps[(wq + g + 8) * 72 + nt * 8 + 2 * t] = h2u(p2, p3);
        }
        ls0 += __shfl_xor_sync(0xffffffffu, ls0, 1);
        ls0 += __shfl_xor_sync(0xffffffffu, ls0, 2);
        ls1 += __shfl_xor_sync(0xffffffffu, ls1, 1);
        ls1 += __shfl_xor_sync(0xffffffffu, ls1, 2);
        l0 = l0 * a0 + ls0;
        l1 = l1 * a1 + ls1;
        m0 = mn0; m1 = mn1;

#pragma unroll
        for (int nt = 0; nt < 16; nt++) {
            o[nt][0] *= a0; o[nt][1] *= a0;
            o[nt][2] *= a1; o[nt][3] *= a1;
        }
        __syncwarp();

        // O += P V : warp 16q x 128d ; k-dim = c (4 chunks of 16)
#pragma unroll
        for (int ks = 0; ks < 4; ks++) {
            uint32_t pa[4];
            const __half* pp = Ps + (wq + g) * 72 + ks * 16 + 2 * t;
            pa[0] = *(const uint32_t*)(pp);
            pa[1] = *(const uint32_t*)(pp + 8 * 72);
            pa[2] = *(const uint32_t*)(pp + 8);
            pa[3] = *(const uint32_t*)(pp + 8 * 72 + 8);
#pragma unroll
            for (int nt = 0; nt < 16; nt++) {
                const __half* vp = Vs + (nt * 8 + g) * 72 + ks * 16 + 2 * t;
                const uint32_t b0 = *(const uint32_t*)(vp);
                const uint32_t b1 = *(const uint32_t*)(vp + 8);
                mma16(o[nt], pa, b0, b1);
            }
        }
        __syncthreads();
    }

    // epilogue: normalize, store ctx halves
    const float il0 = 1.f / l0, il1 = 1.f / l1;
    const int r0 = qb + wq + g, r1 = r0 + 8;
#pragma unroll
    for (int nt = 0; nt < 16; nt++) {
        const int c = nt * 8 + 2 * t;
        *(uint32_t*)&Og[(size_t)r0 * HDc + c] = h2u(o[nt][0] * il0, o[nt][1] * il0);
        *(uint32_t*)&Og[(size_t)r1 * HDc + c] = h2u(o[nt][2] * il1, o[nt][3] * il1);
    }
}

// ---------------------------------------------------------------------------
extern "C" void kernel_launch(void* const* d_in, const int* in_sizes, int n_in,
                              void* d_out, int out_size)
{
    const float* x  = (const float*)d_in[0];
    const float* y  = (const float*)d_in[1];
    const float* Wq = (const float*)d_in[2];
    const float* bq = (const float*)d_in[3];
    const float* Wk = (const float*)d_in[4];
    const float* bk = (const float*)d_in[5];
    const float* Wv = (const float*)d_in[6];
    const float* bv = (const float*)d_in[7];
    const float* Wo = (const float*)d_in[8];
    const float* bo = (const float*)d_in[9];
    float* out = (float*)d_out;

    cudaFuncSetAttribute(flash_attn,
                         cudaFuncAttributeMaxDynamicSharedMemorySize, FLASH_SMEM);
    cudaFuncSetAttribute(gemm_h<0>,
                         cudaFuncAttributeMaxDynamicSharedMemorySize, GEMM_SMEM);
    cudaFuncSetAttribute(gemm_h<1>,
                         cudaFuncAttributeMaxDynamicSharedMemorySize, GEMM_SMEM);
    cudaFuncSetAttribute(gemm_h<2>,
                         cudaFuncAttributeMaxDynamicSharedMemorySize, GEMM_SMEM);

    __half* gx; cudaGetSymbolAddress((void**)&gx, g_xh);
    __half* gy; cudaGetSymbolAddress((void**)&gy, g_yh);
    __half* gw; cudaGetSymbolAddress((void**)&gw, g_wh);
    __half* gq; cudaGetSymbolAddress((void**)&gq, g_qh);
    __half* gk; cudaGetSymbolAddress((void**)&gk, g_kh);
    __half* gvt; cudaGetSymbolAddress((void**)&gvt, g_vt);
    __half* gc; cudaGetSymbolAddress((void**)&gc, g_ch);

    // 1. convert inputs + weights to fp16
    const int nXY4 = (Mc * Dc) / 4;
    const int nW4  = (Dc * Dc) / 4;
    conv_h<<<(nXY4 + 255)/256, 256>>>((const float4*)x,  (uint2*)gx, nXY4);
    conv_h<<<(nXY4 + 255)/256, 256>>>((const float4*)y,  (uint2*)gy, nXY4);
    conv_h<<<(nW4  + 255)/256, 256>>>((const float4*)Wq, (uint2*)(gw + 0*Dc*Dc), nW4);
    conv_h<<<(nW4  + 255)/256, 256>>>((const float4*)Wk, (uint2*)(gw + 1*Dc*Dc), nW4);
    conv_h<<<(nW4  + 255)/256, 256>>>((const float4*)Wv, (uint2*)(gw + 2*Dc*Dc), nW4);
    conv_h<<<(nW4  + 255)/256, 256>>>((const float4*)Wo, (uint2*)(gw + 3*Dc*Dc), nW4);

    // 2. projections
    dim3 gblk(256);
    dim3 ggrid(Dc/128, Mc/256);   // (8, 32)
    gemm_h<0><<<ggrid, gblk, GEMM_SMEM>>>(gx, gw + 0*Dc*Dc, bq, gq,  nullptr);
    gemm_h<0><<<ggrid, gblk, GEMM_SMEM>>>(gy, gw + 1*Dc*Dc, bk, gk,  nullptr);
    gemm_h<2><<<ggrid, gblk, GEMM_SMEM>>>(gy, gw + 2*Dc*Dc, bv, gvt, nullptr);

    // 3. attention
    dim3 fgrid(Tc/128, Bc*Hc);    // (16, 32)
    flash_attn<<<fgrid, gblk, FLASH_SMEM>>>();

    // 4. output projection (reads g_ch, writes fp32 out)
    gemm_h<1><<<ggrid, gblk, GEMM_SMEM>>>(gc, gw + 3*Dc*Dc, bo, nullptr, out);
}

// round 7
// speedup vs baseline: 6.4894x; 1.0533x over previous
#include <cuda_runtime.h>
#include <cuda_fp16.h>
#include <math.h>
#include <stdint.h>

#define Bc  4
#define Tc  2048
#define Dc  1024
#define Hc  8
#define HDc 128
#define Mc  (Bc*Tc)

// Scratch (fp16)
__device__ __half g_qh[Bc*Tc*Dc];           // [B,H,T,HD]
__device__ __half g_kh[Bc*Tc*Dc];           // [B,H,T,HD]
__device__ __half g_vt[Bc*Tc*Dc];           // [B,H,HD,T]  (V transposed)
__device__ __half g_ch[Bc*Tc*Dc];           // ctx [B,H,T,HD]
__device__ __half g_xh[Bc*Tc*Dc];
__device__ __half g_yh[Bc*Tc*Dc];
__device__ __half g_wh[4][Dc*Dc];

// ---------------------------------------------------------------------------
// helpers
// ---------------------------------------------------------------------------
__device__ __forceinline__ uint32_t smem_u32(const void* p) {
    uint32_t a;
    asm("{ .reg .u64 t; cvta.to.shared.u64 t, %1; cvt.u32.u64 %0, t; }"
        : "=r"(a) : "l"(p));
    return a;
}
__device__ __forceinline__ float ex2(float x) {
    float y;
    asm("ex2.approx.f32 %0, %1;" : "=f"(y) : "f"(x));
    return y;
}
__device__ __forceinline__ uint32_t h2u(float a, float b) {
    __half2 h = __floats2half2_rn(a, b);
    return *(uint32_t*)&h;
}
__device__ __forceinline__ void cp16(uint32_t dst, const void* src) {
    asm volatile("cp.async.cg.shared.global [%0], [%1], 16;" :: "r"(dst), "l"(src));
}
#define CP_COMMIT() asm volatile("cp.async.commit_group;" ::: "memory")
#define CP_WAIT2()  asm volatile("cp.async.wait_group 2;" ::: "memory")
#define CP_WAIT1()  asm volatile("cp.async.wait_group 1;" ::: "memory")
#define CP_WAIT0()  asm volatile("cp.async.wait_group 0;" ::: "memory")

// ldmatrix x4 (b16, non-trans): 4 8x8-half matrices. Result matrix m -> r[m];
// within a matrix lane L holds row L/4, cols 2(L%4)..2(L%4)+1.
__device__ __forceinline__ void ldm4(uint32_t addr, uint32_t* r) {
    asm volatile("ldmatrix.sync.aligned.m8n8.x4.shared.b16 {%0,%1,%2,%3}, [%4];"
                 : "=r"(r[0]), "=r"(r[1]), "=r"(r[2]), "=r"(r[3]) : "r"(addr));
}

// m16n8k16 fp16 MMA, f32 accumulate in place.
__device__ __forceinline__ void mma16(float* d, const uint32_t* a,
                                      uint32_t b0, uint32_t b1) {
    asm volatile(
        "mma.sync.aligned.m16n8k16.row.col.f32.f16.f16.f32 "
        "{%0,%1,%2,%3}, {%4,%5,%6,%7}, {%8,%9}, {%0,%1,%2,%3};"
        : "+f"(d[0]), "+f"(d[1]), "+f"(d[2]), "+f"(d[3])
        : "r"(a[0]), "r"(a[1]), "r"(a[2]), "r"(a[3]), "r"(b0), "r"(b1));
}

// ---------------------------------------------------------------------------
// fp32 -> fp16 converts, fused: 2 launches instead of 6
// ---------------------------------------------------------------------------
__global__ void conv_h2(const float4* __restrict__ a, uint2* __restrict__ oa,
                        const float4* __restrict__ b, uint2* __restrict__ ob,
                        int n4) {
    int i = blockIdx.x * blockDim.x + threadIdx.x;
    const float4* s = blockIdx.y ? b : a;
    uint2* d = blockIdx.y ? ob : oa;
    if (i < n4) {
        float4 v = s[i];
        uint2 o;
        o.x = h2u(v.x, v.y);
        o.y = h2u(v.z, v.w);
        d[i] = o;
    }
}

__global__ void conv_h4(const float4* __restrict__ w0, const float4* __restrict__ w1,
                        const float4* __restrict__ w2, const float4* __restrict__ w3,
                        uint2* __restrict__ o0, int n4) {
    int i = blockIdx.x * blockDim.x + threadIdx.x;
    const float4* s = (blockIdx.y == 0) ? w0 : (blockIdx.y == 1) ? w1
                      : (blockIdx.y == 2) ? w2 : w3;
    uint2* d = o0 + (size_t)blockIdx.y * (Dc * Dc / 4);
    if (i < n4) {
        float4 v = s[i];
        uint2 o;
        o.x = h2u(v.x, v.y);
        o.y = h2u(v.z, v.w);
        d[i] = o;
    }
}

// ---------------------------------------------------------------------------
// fp16 warp-MMA GEMM: out[m,n] = sum_k A[m,k]*W[n,k] + bias[n]
// CTA tile 256x128, 8 warps (warp 64x64), K-chunk 32 halves, 3-stage cp.async,
// ldmatrix fragments.
// MODE 0: A half [M,K]; out half head layout. MODE 1: A from g_ch head layout,
// out float plain. MODE 2: out half V^T layout (smem-staged transpose).
// ---------------------------------------------------------------------------
#define GEMM_SMEM (3*30720)

template<int MODE>
__global__ __launch_bounds__(256, 1)
void gemm_h(const __half* __restrict__ A, const __half* __restrict__ Wg,
            const float* __restrict__ bias, __half* __restrict__ outh,
            float* __restrict__ outf)
{
    extern __shared__ __align__(16) char smemc[];
    const uint32_t sb = smem_u32(smemc);

    const int tid = threadIdx.x;
    const int wid = tid >> 5, lane = tid & 31;
    const int g = lane >> 2, t = lane & 3;
    const int wm = (wid & 3) * 64, wn = (wid >> 2) * 64;
    const int bn = blockIdx.x * 128, bm = blockIdx.y * 256;

    // ldmatrix lane-address components
    const int a_row = lane & 15, a_col8 = ((lane >> 4) & 1) * 8;     // A frags
    const int b_rgrp = (lane >> 4) & 1, b_row = lane & 7;            // B frags
    const int b_col8 = ((lane >> 3) & 1) * 8;

    auto issue = [&](int stg, int k0) {
        const uint32_t da = sb + (uint32_t)(stg * 30720);
        const uint32_t db = da + 20480u;
#pragma unroll
        for (int it = 0; it < 4; it++) {
            const int idx = tid + it * 256;
            const int row = idx >> 2, s = idx & 3;
            const __half* src;
            if (MODE == 1) {
                const int m = bm + row, b = m >> 11, tt = m & 2047;
                const int kg = k0 + s * 8;
                const int h = kg >> 7, d = kg & 127;
                src = A + (((size_t)(b * Hc + h) * Tc + tt) * HDc + d);
            } else {
                src = A + (size_t)(bm + row) * Dc + k0 + s * 8;
            }
            cp16(da + (uint32_t)(row * 40 + s * 8) * 2u, src);
        }
#pragma unroll
        for (int it = 0; it < 2; it++) {
            const int idx = tid + it * 256;
            const int row = idx >> 2, s = idx & 3;
            cp16(db + (uint32_t)(row * 40 + s * 8) * 2u,
                 Wg + (size_t)(bn + row) * Dc + k0 + s * 8);
        }
        CP_COMMIT();
    };

    float c[4][8][4];
#pragma unroll
    for (int mt = 0; mt < 4; mt++)
#pragma unroll
        for (int nt = 0; nt < 8; nt++)
#pragma unroll
            for (int j = 0; j < 4; j++) c[mt][nt][j] = 0.f;

    issue(0, 0); issue(1, 32); issue(2, 64);

    for (int i = 0; i < 32; i++) {
        if (i < 30)      { CP_WAIT2(); }
        else if (i == 30){ CP_WAIT1(); }
        else             { CP_WAIT0(); }
        __syncthreads();

        const uint32_t as = sb + (uint32_t)((i % 3) * 30720);
        const uint32_t bs = as + 20480u;

#pragma unroll
        for (int ks = 0; ks < 2; ks++) {
            const int kk = ks * 16;
            uint32_t a[4][4];
#pragma unroll
            for (int mt = 0; mt < 4; mt++)
                ldm4(as + (uint32_t)((wm + mt * 16 + a_row) * 40 + kk + a_col8) * 2u,
                     a[mt]);
#pragma unroll
            for (int j = 0; j < 4; j++) {
                uint32_t br[4];
                ldm4(bs + (uint32_t)((wn + (2 * j + b_rgrp) * 8 + b_row) * 40
                                     + kk + b_col8) * 2u, br);
#pragma unroll
                for (int mt = 0; mt < 4; mt++) {
                    mma16(c[mt][2 * j],     a[mt], br[0], br[1]);
                    mma16(c[mt][2 * j + 1], a[mt], br[2], br[3]);
                }
            }
        }
        __syncthreads();
        if (i + 3 < 32) issue((i + 3) % 3, (i + 3) * 32);
    }

    const int b0i_base = bm >> 11, t0 = bm & 2047;
    const int h = bn >> 7;

    if (MODE == 2) {
        __half* Ts = (__half*)smemc;          // [128 n][264] halves
#pragma unroll
        for (int mt = 0; mt < 4; mt++) {
            const int r0l = wm + mt * 16 + g, r1l = r0l + 8;
#pragma unroll
            for (int nt = 0; nt < 8; nt++) {
                const int cl = wn + nt * 8 + 2 * t;
                const float bx = __ldg(bias + bn + cl);
                const float by = __ldg(bias + bn + cl + 1);
                Ts[(cl    ) * 264 + r0l] = __float2half_rn(c[mt][nt][0] + bx);
                Ts[(cl + 1) * 264 + r0l] = __float2half_rn(c[mt][nt][1] + by);
                Ts[(cl    ) * 264 + r1l] = __float2half_rn(c[mt][nt][2] + bx);
                Ts[(cl + 1) * 264 + r1l] = __float2half_rn(c[mt][nt][3] + by);
            }
        }
        __syncthreads();
#pragma unroll
        for (int it = 0; it < 16; it++) {
            const int idx = tid + it * 256;
            const int row = idx >> 5, s = idx & 31;
            const uint4 v = *(const uint4*)&Ts[row * 264 + s * 8];
            *(uint4*)&outh[(((size_t)(b0i_base * Hc + h) * HDc + row)
                            * Tc) + t0 + s * 8] = v;
        }
        return;
    }

#pragma unroll
    for (int mt = 0; mt < 4; mt++) {
        const int r0 = bm + wm + mt * 16 + g;
        const int r1 = r0 + 8;
#pragma unroll
        for (int nt = 0; nt < 8; nt++) {
            const int cl = wn + nt * 8 + 2 * t;
            const int col = bn + cl;
            const float bx = __ldg(bias + col), by = __ldg(bias + col + 1);
            const float v00 = c[mt][nt][0] + bx, v01 = c[mt][nt][1] + by;
            const float v10 = c[mt][nt][2] + bx, v11 = c[mt][nt][3] + by;
            if (MODE == 0) {
                const int b0i = r0 >> 11, t0i = r0 & 2047;
                const int b1i = r1 >> 11, t1i = r1 & 2047;
                *(uint32_t*)&outh[(((size_t)(b0i * Hc + h) * Tc + t0i) * HDc) + cl]
                    = h2u(v00, v01);
                *(uint32_t*)&outh[(((size_t)(b1i * Hc + h) * Tc + t1i) * HDc) + cl]
                    = h2u(v10, v11);
            } else {
                *(float2*)&outf[(size_t)r0 * Dc + col] = make_float2(v00, v01);
                *(float2*)&outf[(size_t)r1 * Dc + col] = make_float2(v10, v11);
            }
        }
    }
}

// ---------------------------------------------------------------------------
// Flash attention fp16 (round-6 structure + ldmatrix fragments + reversed qt)
// ---------------------------------------------------------------------------
#define FLASH_SMEM 90112
#define HK0  0
#define HK1  8704
#define HV0  17408
#define HV1  26624
#define HPS  35840

__global__ __launch_bounds__(256)
void flash_attn()
{
    extern __shared__ __align__(16) __half fsm[];
    const uint32_t sb = smem_u32(fsm);

    const int bh  = blockIdx.y;
    const int qt  = gridDim.x - 1 - blockIdx.x;    // longest blocks first
    const int qb  = qt * 128;
    const int tid = threadIdx.x;
    const int wid = tid >> 5, lane = tid & 31;
    const int g = lane >> 2, t = lane & 3;
    const int wq = wid * 16;

    // ldmatrix lane-address components
    const int a_row = lane & 15, a_col8 = ((lane >> 4) & 1) * 8;
    const int b_rgrp = (lane >> 4) & 1, b_row = lane & 7;
    const int b_col8 = ((lane >> 3) & 1) * 8;

    const __half* Qg  = g_qh + (size_t)bh * Tc * HDc;
    const __half* Kg  = g_kh + (size_t)bh * Tc * HDc;
    const __half* Vtg = g_vt + (size_t)bh * HDc * Tc;
    __half*       Og  = g_ch + (size_t)bh * Tc * HDc;

    __half* Ps = fsm + HPS;
    const uint32_t psb = sb + HPS * 2u;

    // Q fragments, held all loop
    uint32_t qf[8][4];
    {
        const int r0 = qb + wq + g, r1 = r0 + 8;
#pragma unroll
        for (int ds = 0; ds < 8; ds++) {
            qf[ds][0] = *(const uint32_t*)&Qg[(size_t)r0 * HDc + ds * 16 + 2 * t];
            qf[ds][1] = *(const uint32_t*)&Qg[(size_t)r1 * HDc + ds * 16 + 2 * t];
            qf[ds][2] = *(const uint32_t*)&Qg[(size_t)r0 * HDc + ds * 16 + 8 + 2 * t];
            qf[ds][3] = *(const uint32_t*)&Qg[(size_t)r1 * HDc + ds * 16 + 8 + 2 * t];
        }
    }

    float o[16][4];
#pragma unroll
    for (int nt = 0; nt < 16; nt++)
#pragma unroll
        for (int j = 0; j < 4; j++) o[nt][j] = 0.f;

    float m0 = -1e30f, m1 = -1e30f, l0 = 0.f, l1 = 0.f;
    const int ktmax = 2 * qt + 1;

    auto issue_kv = [&](int buf, int kt) {
        const int kb = kt * 64;
        const uint32_t kd = sb + (buf ? HK1 : HK0) * 2u;
        const uint32_t vd = sb + (buf ? HV1 : HV0) * 2u;
#pragma unroll
        for (int it = 0; it < 4; it++) {
            const int idx = tid + it * 256;
            const int c = idx >> 4, s = idx & 15;
            cp16(kd + (uint32_t)(c * 136 + s * 8) * 2u,
                 Kg + (size_t)(kb + c) * HDc + s * 8);
        }
#pragma unroll
        for (int it = 0; it < 4; it++) {
            const int idx = tid + it * 256;
            const int d = idx >> 3, s = idx & 7;
            cp16(vd + (uint32_t)(d * 72 + s * 8) * 2u,
                 Vtg + (size_t)d * Tc + kb + s * 8);
        }
        CP_COMMIT();
    };

    issue_kv(0, 0);

    const float Csc = 0.12751743342f;   // (1/sqrt(128)) * log2(e)

    for (int kt = 0; kt <= ktmax; kt++) {
        const int cur = kt & 1;
        if (kt < ktmax) {
            issue_kv(1 - cur, kt + 1);
            CP_WAIT1();
        } else {
            CP_WAIT0();
        }
        __syncthreads();

        const uint32_t ks_b = sb + (cur ? HK1 : HK0) * 2u;
        const uint32_t vs_b = sb + (cur ? HV1 : HV0) * 2u;
        const int kb = kt * 64;

        // S = Q K^T : warp 16q x 64c
        float s[8][4];
#pragma unroll
        for (int nt = 0; nt < 8; nt++)
#pragma unroll
            for (int j = 0; j < 4; j++) s[nt][j] = 0.f;

#pragma unroll
        for (int ds = 0; ds < 8; ds++) {
#pragma unroll
            for (int j = 0; j < 4; j++) {
                uint32_t br[4];
                ldm4(ks_b + (uint32_t)(((2 * j + b_rgrp) * 8 + b_row) * 136
                                       + ds * 16 + b_col8) * 2u, br);
                mma16(s[2 * j],     qf[ds], br[0], br[1]);
                mma16(s[2 * j + 1], qf[ds], br[2], br[3]);
            }
        }

        // scale + causal mask
        const int qr0 = qb + wq + g, qr1 = qr0 + 8;
        const bool needm = (kt >= 2 * qt);
#pragma unroll
        for (int nt = 0; nt < 8; nt++) {
            const int c0 = kb + nt * 8 + 2 * t;
            float v0 = s[nt][0] * Csc, v1 = s[nt][1] * Csc;
            float v2 = s[nt][2] * Csc, v3 = s[nt][3] * Csc;
            if (needm) {
                if (c0     > qr0) v0 = -1e30f;
                if (c0 + 1 > qr0) v1 = -1e30f;
                if (c0     > qr1) v2 = -1e30f;
                if (c0 + 1 > qr1) v3 = -1e30f;
            }
            s[nt][0] = v0; s[nt][1] = v1; s[nt][2] = v2; s[nt][3] = v3;
        }

        // online softmax
        float mx0 = -1e30f, mx1 = -1e30f;
#pragma unroll
        for (int nt = 0; nt < 8; nt++) {
            mx0 = fmaxf(mx0, fmaxf(s[nt][0], s[nt][1]));
            mx1 = fmaxf(mx1, fmaxf(s[nt][2], s[nt][3]));
        }
        mx0 = fmaxf(mx0, __shfl_xor_sync(0xffffffffu, mx0, 1));
        mx0 = fmaxf(mx0, __shfl_xor_sync(0xffffffffu, mx0, 2));
        mx1 = fmaxf(mx1, __shfl_xor_sync(0xffffffffu, mx1, 1));
        mx1 = fmaxf(mx1, __shfl_xor_sync(0xffffffffu, mx1, 2));

        const float mn0 = fmaxf(m0, mx0), mn1 = fmaxf(m1, mx1);
        const float a0 = ex2(m0 - mn0), a1 = ex2(m1 - mn1);

        float ls0 = 0.f, ls1 = 0.f;
#pragma unroll
        for (int nt = 0; nt < 8; nt++) {
            const float p0 = ex2(s[nt][0] - mn0);
            const float p1 = ex2(s[nt][1] - mn0);
            const float p2 = ex2(s[nt][2] - mn1);
            const float p3 = ex2(s[nt][3] - mn1);
            ls0 += p0 + p1; ls1 += p2 + p3;
            *(uint32_t*)&Ps[(wq + g) * 72 + nt * 8 + 2 * t]     = h2u(p0, p1);
            *(uint32_t*)&Ps[(wq + g + 8) * 72 + nt * 8 + 2 * t] = h2u(p2, p3);
        }
        ls0 += __shfl_xor_sync(0xffffffffu, ls0, 1);
        ls0 += __shfl_xor_sync(0xffffffffu, ls0, 2);
        ls1 += __shfl_xor_sync(0xffffffffu, ls1, 1);
        ls1 += __shfl_xor_sync(0xffffffffu, ls1, 2);
        l0 = l0 * a0 + ls0;
        l1 = l1 * a1 + ls1;
        m0 = mn0; m1 = mn1;

#pragma unroll
        for (int nt = 0; nt < 16; nt++) {
            o[nt][0] *= a0; o[nt][1] *= a0;
            o[nt][2] *= a1; o[nt][3] *= a1;
        }
        __syncwarp();

        // O += P V : warp 16q x 128d
#pragma unroll
        for (int ks = 0; ks < 4; ks++) {
            uint32_t pa[4];
            ldm4(psb + (uint32_t)((wq + a_row) * 72 + ks * 16 + a_col8) * 2u,
                 pa);
#pragma unroll
            for (int j = 0; j < 8; j++) {
                uint32_t vb[4];
                ldm4(vs_b + (uint32_t)(((2 * j + b_rgrp) * 8 + b_row) * 72
                                       + ks * 16 + b_col8) * 2u, vb);
                mma16(o[2 * j],     pa, vb[0], vb[1]);
                mma16(o[2 * j + 1], pa, vb[2], vb[3]);
            }
        }
        __syncthreads();
    }

    // epilogue
    const float il0 = 1.f / l0, il1 = 1.f / l1;
    const int r0 = qb + wq + g, r1 = r0 + 8;
#pragma unroll
    for (int nt = 0; nt < 16; nt++) {
        const int c = nt * 8 + 2 * t;
        *(uint32_t*)&Og[(size_t)r0 * HDc + c] = h2u(o[nt][0] * il0, o[nt][1] * il0);
        *(uint32_t*)&Og[(size_t)r1 * HDc + c] = h2u(o[nt][2] * il1, o[nt][3] * il1);
    }
}

// ---------------------------------------------------------------------------
extern "C" void kernel_launch(void* const* d_in, const int* in_sizes, int n_in,
                              void* d_out, int out_size)
{
    const float* x  = (const float*)d_in[0];
    const float* y  = (const float*)d_in[1];
    const float* Wq = (const float*)d_in[2];
    const float* bq = (const float*)d_in[3];
    const float* Wk = (const float*)d_in[4];
    const float* bk = (const float*)d_in[5];
    const float* Wv = (const float*)d_in[6];
    const float* bv = (const float*)d_in[7];
    const float* Wo = (const float*)d_in[8];
    const float* bo = (const float*)d_in[9];
    float* out = (float*)d_out;

    cudaFuncSetAttribute(flash_attn,
                         cudaFuncAttributeMaxDynamicSharedMemorySize, FLASH_SMEM);
    cudaFuncSetAttribute(gemm_h<0>,
                         cudaFuncAttributeMaxDynamicSharedMemorySize, GEMM_SMEM);
    cudaFuncSetAttribute(gemm_h<1>,
                         cudaFuncAttributeMaxDynamicSharedMemorySize, GEMM_SMEM);
    cudaFuncSetAttribute(gemm_h<2>,
                         cudaFuncAttributeMaxDynamicSharedMemorySize, GEMM_SMEM);

    __half* gx; cudaGetSymbolAddress((void**)&gx, g_xh);
    __half* gy; cudaGetSymbolAddress((void**)&gy, g_yh);
    __half* gw; cudaGetSymbolAddress((void**)&gw, g_wh);
    __half* gq; cudaGetSymbolAddress((void**)&gq, g_qh);
    __half* gk; cudaGetSymbolAddress((void**)&gk, g_kh);
    __half* gvt; cudaGetSymbolAddress((void**)&gvt, g_vt);
    __half* gc; cudaGetSymbolAddress((void**)&gc, g_ch);

    // 1. convert inputs + weights to fp16 (2 fused launches)
    const int nXY4 = (Mc * Dc) / 4;
    const int nW4  = (Dc * Dc) / 4;
    conv_h2<<<dim3((nXY4 + 255)/256, 2), 256>>>(
        (const float4*)x, (uint2*)gx, (const float4*)y, (uint2*)gy, nXY4);
    conv_h4<<<dim3((nW4 + 255)/256, 4), 256>>>(
        (const float4*)Wq, (const float4*)Wk, (const float4*)Wv,
        (const float4*)Wo, (uint2*)gw, nW4);

    // 2. projections
    dim3 gblk(256);
    dim3 ggrid(Dc/128, Mc/256);   // (8, 32)
    gemm_h<0><<<ggrid, gblk, GEMM_SMEM>>>(gx, gw + 0*Dc*Dc, bq, gq,  nullptr);
    gemm_h<0><<<ggrid, gblk, GEMM_SMEM>>>(gy, gw + 1*Dc*Dc, bk, gk,  nullptr);
    gemm_h<2><<<ggrid, gblk, GEMM_SMEM>>>(gy, gw + 2*Dc*Dc, bv, gvt, nullptr);

    // 3. attention
    dim3 fgrid(Tc/128, Bc*Hc);    // (16, 32)
    flash_attn<<<fgrid, gblk, FLASH_SMEM>>>();

    // 4. output projection
    gemm_h<1><<<ggrid, gblk, GEMM_SMEM>>>(gc, gw + 3*Dc*Dc, bo, nullptr, out);
}

// round 8
// speedup vs baseline: 7.5518x; 1.1637x over previous
#include <cuda_runtime.h>
#include <cuda_fp16.h>
#include <math.h>
#include <stdint.h>

#define Bc  4
#define Tc  2048
#define Dc  1024
#define Hc  8
#define HDc 128
#define Mc  (Bc*Tc)

// Scratch (fp16)
__device__ __half g_qh[Bc*Tc*Dc];           // [B,H,T,HD]
__device__ __half g_kh[Bc*Tc*Dc];           // [B,H,T,HD]
__device__ __half g_vt[Bc*Tc*Dc];           // [B,H,HD,T]  (V transposed)
__device__ __half g_ch[Bc*Tc*Dc];           // ctx [B,H,T,HD]
__device__ __half g_xh[Bc*Tc*Dc];
__device__ __half g_yh[Bc*Tc*Dc];
__device__ __half g_wh[4][Dc*Dc];

// ---------------------------------------------------------------------------
// helpers
// ---------------------------------------------------------------------------
__device__ __forceinline__ uint32_t smem_u32(const void* p) {
    uint32_t a;
    asm("{ .reg .u64 t; cvta.to.shared.u64 t, %1; cvt.u32.u64 %0, t; }"
        : "=r"(a) : "l"(p));
    return a;
}
__device__ __forceinline__ float ex2(float x) {
    float y;
    asm("ex2.approx.f32 %0, %1;" : "=f"(y) : "f"(x));
    return y;
}
__device__ __forceinline__ uint32_t h2u(float a, float b) {
    __half2 h = __floats2half2_rn(a, b);
    return *(uint32_t*)&h;
}
__device__ __forceinline__ void cp16(uint32_t dst, const void* src) {
    asm volatile("cp.async.cg.shared.global [%0], [%1], 16;" :: "r"(dst), "l"(src));
}
#define CP_COMMIT() asm volatile("cp.async.commit_group;" ::: "memory")
#define CP_WAIT2()  asm volatile("cp.async.wait_group 2;" ::: "memory")
#define CP_WAIT1()  asm volatile("cp.async.wait_group 1;" ::: "memory")
#define CP_WAIT0()  asm volatile("cp.async.wait_group 0;" ::: "memory")

// ldmatrix x4 (b16, non-trans)
__device__ __forceinline__ void ldm4(uint32_t addr, uint32_t* r) {
    asm volatile("ldmatrix.sync.aligned.m8n8.x4.shared.b16 {%0,%1,%2,%3}, [%4];"
                 : "=r"(r[0]), "=r"(r[1]), "=r"(r[2]), "=r"(r[3]) : "r"(addr));
}

// m16n8k16 fp16 MMA, f32 accumulate in place.
__device__ __forceinline__ void mma16(float* d, const uint32_t* a,
                                      uint32_t b0, uint32_t b1) {
    asm volatile(
        "mma.sync.aligned.m16n8k16.row.col.f32.f16.f16.f32 "
        "{%0,%1,%2,%3}, {%4,%5,%6,%7}, {%8,%9}, {%0,%1,%2,%3};"
        : "+f"(d[0]), "+f"(d[1]), "+f"(d[2]), "+f"(d[3])
        : "r"(a[0]), "r"(a[1]), "r"(a[2]), "r"(a[3]), "r"(b0), "r"(b1));
}

// ---------------------------------------------------------------------------
// fp32 -> fp16 converts (2 fused launches)
// ---------------------------------------------------------------------------
__global__ void conv_h2(const float4* __restrict__ a, uint2* __restrict__ oa,
                        const float4* __restrict__ b, uint2* __restrict__ ob,
                        int n4) {
    int i = blockIdx.x * blockDim.x + threadIdx.x;
    const float4* s = blockIdx.y ? b : a;
    uint2* d = blockIdx.y ? ob : oa;
    if (i < n4) {
        float4 v = s[i];
        uint2 o;
        o.x = h2u(v.x, v.y);
        o.y = h2u(v.z, v.w);
        d[i] = o;
    }
}

__global__ void conv_h4(const float4* __restrict__ w0, const float4* __restrict__ w1,
                        const float4* __restrict__ w2, const float4* __restrict__ w3,
                        uint2* __restrict__ o0, int n4) {
    int i = blockIdx.x * blockDim.x + threadIdx.x;
    const float4* s = (blockIdx.y == 0) ? w0 : (blockIdx.y == 1) ? w1
                      : (blockIdx.y == 2) ? w2 : w3;
    uint2* d = o0 + (size_t)blockIdx.y * (Dc * Dc / 4);
    if (i < n4) {
        float4 v = s[i];
        uint2 o;
        o.x = h2u(v.x, v.y);
        o.y = h2u(v.z, v.w);
        d[i] = o;
    }
}

// ---------------------------------------------------------------------------
// fp16 warp-MMA GEMM: out[m,n] = sum_k A[m,k]*W[n,k] + bias[n]
// CTA tile 128x128, 8 warps (warp 32x64), K-chunk 32 halves, 3-stage cp.async,
// ldmatrix fragments, 2 CTAs/SM.
// MODE 0: A half [M,K]; out half head layout. MODE 1: A from g_ch head layout,
// out float plain. MODE 2: out half V^T layout (smem-staged transpose).
// smem stage: A 128x40 + B 128x40 halves = 20480B; x3 = 61440B
// ---------------------------------------------------------------------------
#define GEMM_SMEM (3*20480)

template<int MODE>
__global__ __launch_bounds__(256, 2)
void gemm_h(const __half* __restrict__ A, const __half* __restrict__ Wg,
            const float* __restrict__ bias, __half* __restrict__ outh,
            float* __restrict__ outf)
{
    extern __shared__ __align__(16) char smemc[];
    const uint32_t sb = smem_u32(smemc);

    const int tid = threadIdx.x;
    const int wid = tid >> 5, lane = tid & 31;
    const int g = lane >> 2, t = lane & 3;
    const int wm = (wid & 3) * 32, wn = (wid >> 2) * 64;
    const int bn = blockIdx.x * 128, bm = blockIdx.y * 128;

    const int a_row = lane & 15, a_col8 = ((lane >> 4) & 1) * 8;
    const int b_rgrp = (lane >> 4) & 1, b_row = lane & 7;
    const int b_col8 = ((lane >> 3) & 1) * 8;

    auto issue = [&](int stg, int k0) {
        const uint32_t da = sb + (uint32_t)(stg * 20480);
        const uint32_t db = da + 10240u;
#pragma unroll
        for (int it = 0; it < 2; it++) {
            const int idx = tid + it * 256;          // 0..511
            const int row = idx >> 2, s = idx & 3;
            const __half* src;
            if (MODE == 1) {
                const int m = bm + row, b = m >> 11, tt = m & 2047;
                const int kg = k0 + s * 8;
                const int h = kg >> 7, d = kg & 127;
                src = A + (((size_t)(b * Hc + h) * Tc + tt) * HDc + d);
            } else {
                src = A + (size_t)(bm + row) * Dc + k0 + s * 8;
            }
            cp16(da + (uint32_t)(row * 40 + s * 8) * 2u, src);
        }
#pragma unroll
        for (int it = 0; it < 2; it++) {
            const int idx = tid + it * 256;
            const int row = idx >> 2, s = idx & 3;
            cp16(db + (uint32_t)(row * 40 + s * 8) * 2u,
                 Wg + (size_t)(bn + row) * Dc + k0 + s * 8);
        }
        CP_COMMIT();
    };

    float c[2][8][4];
#pragma unroll
    for (int mt = 0; mt < 2; mt++)
#pragma unroll
        for (int nt = 0; nt < 8; nt++)
#pragma unroll
            for (int j = 0; j < 4; j++) c[mt][nt][j] = 0.f;

    issue(0, 0); issue(1, 32); issue(2, 64);

    for (int i = 0; i < 32; i++) {
        if (i < 30)      { CP_WAIT2(); }
        else if (i == 30){ CP_WAIT1(); }
        else             { CP_WAIT0(); }
        __syncthreads();

        const uint32_t as = sb + (uint32_t)((i % 3) * 20480);
        const uint32_t bs = as + 10240u;

#pragma unroll
        for (int ks = 0; ks < 2; ks++) {
            const int kk = ks * 16;
            uint32_t a[2][4];
#pragma unroll
            for (int mt = 0; mt < 2; mt++)
                ldm4(as + (uint32_t)((wm + mt * 16 + a_row) * 40 + kk + a_col8) * 2u,
                     a[mt]);
#pragma unroll
            for (int j = 0; j < 4; j++) {
                uint32_t br[4];
                ldm4(bs + (uint32_t)((wn + (2 * j + b_rgrp) * 8 + b_row) * 40
                                     + kk + b_col8) * 2u, br);
#pragma unroll
                for (int mt = 0; mt < 2; mt++) {
                    mma16(c[mt][2 * j],     a[mt], br[0], br[1]);
                    mma16(c[mt][2 * j + 1], a[mt], br[2], br[3]);
                }
            }
        }
        __syncthreads();
        if (i + 3 < 32) issue((i + 3) % 3, (i + 3) * 32);
    }

    const int b0i_base = bm >> 11, t0 = bm & 2047;
    const int h = bn >> 7;

    if (MODE == 2) {
        __half* Ts = (__half*)smemc;          // [128 n][136] halves
#pragma unroll
        for (int mt = 0; mt < 2; mt++) {
            const int r0l = wm + mt * 16 + g, r1l = r0l + 8;
#pragma unroll
            for (int nt = 0; nt < 8; nt++) {
                const int cl = wn + nt * 8 + 2 * t;
                const float bx = __ldg(bias + bn + cl);
                const float by = __ldg(bias + bn + cl + 1);
                Ts[(cl    ) * 136 + r0l] = __float2half_rn(c[mt][nt][0] + bx);
                Ts[(cl + 1) * 136 + r0l] = __float2half_rn(c[mt][nt][1] + by);
                Ts[(cl    ) * 136 + r1l] = __float2half_rn(c[mt][nt][2] + bx);
                Ts[(cl + 1) * 136 + r1l] = __float2half_rn(c[mt][nt][3] + by);
            }
        }
        __syncthreads();
#pragma unroll
        for (int it = 0; it < 8; it++) {
            const int idx = tid + it * 256;          // 0..2047
            const int row = idx >> 4, s = idx & 15;
            const uint4 v = *(const uint4*)&Ts[row * 136 + s * 8];
            *(uint4*)&outh[(((size_t)(b0i_base * Hc + h) * HDc + row)
                            * Tc) + t0 + s * 8] = v;
        }
        return;
    }

#pragma unroll
    for (int mt = 0; mt < 2; mt++) {
        const int r0 = bm + wm + mt * 16 + g;
        const int r1 = r0 + 8;
#pragma unroll
        for (int nt = 0; nt < 8; nt++) {
            const int cl = wn + nt * 8 + 2 * t;
            const int col = bn + cl;
            const float bx = __ldg(bias + col), by = __ldg(bias + col + 1);
            const float v00 = c[mt][nt][0] + bx, v01 = c[mt][nt][1] + by;
            const float v10 = c[mt][nt][2] + bx, v11 = c[mt][nt][3] + by;
            if (MODE == 0) {
                const int b0i = r0 >> 11, t0i = r0 & 2047;
                const int b1i = r1 >> 11, t1i = r1 & 2047;
                *(uint32_t*)&outh[(((size_t)(b0i * Hc + h) * Tc + t0i) * HDc) + cl]
                    = h2u(v00, v01);
                *(uint32_t*)&outh[(((size_t)(b1i * Hc + h) * Tc + t1i) * HDc) + cl]
                    = h2u(v10, v11);
            } else {
                *(float2*)&outf[(size_t)r0 * Dc + col] = make_float2(v00, v01);
                *(float2*)&outf[(size_t)r1 * Dc + col] = make_float2(v10, v11);
            }
        }
    }
}

// ---------------------------------------------------------------------------
// Flash attention fp16: 128 threads / 4 warps; Q tile 64 (warp 16 q-rows),
// K tile 64; ldmatrix fragments; double-buffered K/V; reversed qt order.
// smem halves: K0[64][136] K1 | V0[128][72] V1 | Ps[64][72]
//            = 8704*2 + 9216*2 + 4608 = 40448 h = 80896 B -> 2 CTAs/SM
// ---------------------------------------------------------------------------
#define FLASH_SMEM 80896
#define HK0  0
#define HK1  8704
#define HV0  17408
#define HV1  26624
#define HPS  35840

__global__ __launch_bounds__(128, 2)
void flash_attn()
{
    extern __shared__ __align__(16) __half fsm[];
    const uint32_t sb = smem_u32(fsm);

    const int bh  = blockIdx.y;
    const int qt  = gridDim.x - 1 - blockIdx.x;    // longest blocks first
    const int qb  = qt * 64;
    const int tid = threadIdx.x;
    const int wid = tid >> 5, lane = tid & 31;
    const int g = lane >> 2, t = lane & 3;
    const int wq = wid * 16;

    const int a_row = lane & 15, a_col8 = ((lane >> 4) & 1) * 8;
    const int b_rgrp = (lane >> 4) & 1, b_row = lane & 7;
    const int b_col8 = ((lane >> 3) & 1) * 8;

    const __half* Qg  = g_qh + (size_t)bh * Tc * HDc;
    const __half* Kg  = g_kh + (size_t)bh * Tc * HDc;
    const __half* Vtg = g_vt + (size_t)bh * HDc * Tc;
    __half*       Og  = g_ch + (size_t)bh * Tc * HDc;

    __half* Ps = fsm + HPS;
    const uint32_t psb = sb + HPS * 2u;

    // Q fragments, held all loop
    uint32_t qf[8][4];
    {
        const int r0 = qb + wq + g, r1 = r0 + 8;
#pragma unroll
        for (int ds = 0; ds < 8; ds++) {
            qf[ds][0] = *(const uint32_t*)&Qg[(size_t)r0 * HDc + ds * 16 + 2 * t];
            qf[ds][1] = *(const uint32_t*)&Qg[(size_t)r1 * HDc + ds * 16 + 2 * t];
            qf[ds][2] = *(const uint32_t*)&Qg[(size_t)r0 * HDc + ds * 16 + 8 + 2 * t];
            qf[ds][3] = *(const uint32_t*)&Qg[(size_t)r1 * HDc + ds * 16 + 8 + 2 * t];
        }
    }

    float o[16][4];
#pragma unroll
    for (int nt = 0; nt < 16; nt++)
#pragma unroll
        for (int j = 0; j < 4; j++) o[nt][j] = 0.f;

    float m0 = -1e30f, m1 = -1e30f, l0 = 0.f, l1 = 0.f;
    const int ktmax = qt;

    auto issue_kv = [&](int buf, int kt) {
        const int kb = kt * 64;
        const uint32_t kd = sb + (buf ? HK1 : HK0) * 2u;
        const uint32_t vd = sb + (buf ? HV1 : HV0) * 2u;
#pragma unroll
        for (int it = 0; it < 8; it++) {
            const int idx = tid + it * 128;          // 0..1023
            const int c = idx >> 4, s = idx & 15;
            cp16(kd + (uint32_t)(c * 136 + s * 8) * 2u,
                 Kg + (size_t)(kb + c) * HDc + s * 8);
        }
#pragma unroll
        for (int it = 0; it < 8; it++) {
            const int idx = tid + it * 128;          // 0..1023
            const int d = idx >> 3, s = idx & 7;
            cp16(vd + (uint32_t)(d * 72 + s * 8) * 2u,
                 Vtg + (size_t)d * Tc + kb + s * 8);
        }
        CP_COMMIT();
    };

    issue_kv(0, 0);

    const float Csc = 0.12751743342f;   // (1/sqrt(128)) * log2(e)

    for (int kt = 0; kt <= ktmax; kt++) {
        const int cur = kt & 1;
        if (kt < ktmax) {
            issue_kv(1 - cur, kt + 1);
            CP_WAIT1();
        } else {
            CP_WAIT0();
        }
        __syncthreads();

        const uint32_t ks_b = sb + (cur ? HK1 : HK0) * 2u;
        const uint32_t vs_b = sb + (cur ? HV1 : HV0) * 2u;
        const int kb = kt * 64;

        // S = Q K^T : warp 16q x 64c
        float s[8][4];
#pragma unroll
        for (int nt = 0; nt < 8; nt++)
#pragma unroll
            for (int j = 0; j < 4; j++) s[nt][j] = 0.f;

#pragma unroll
        for (int ds = 0; ds < 8; ds++) {
#pragma unroll
            for (int j = 0; j < 4; j++) {
                uint32_t br[4];
                ldm4(ks_b + (uint32_t)(((2 * j + b_rgrp) * 8 + b_row) * 136
                                       + ds * 16 + b_col8) * 2u, br);
                mma16(s[2 * j],     qf[ds], br[0], br[1]);
                mma16(s[2 * j + 1], qf[ds], br[2], br[3]);
            }
        }

        // scale + causal mask (diagonal tile only)
        const int qr0 = qb + wq + g, qr1 = qr0 + 8;
        const bool needm = (kt == qt);
#pragma unroll
        for (int nt = 0; nt < 8; nt++) {
            const int c0 = kb + nt * 8 + 2 * t;
            float v0 = s[nt][0] * Csc, v1 = s[nt][1] * Csc;
            float v2 = s[nt][2] * Csc, v3 = s[nt][3] * Csc;
            if (needm) {
                if (c0     > qr0) v0 = -1e30f;
                if (c0 + 1 > qr0) v1 = -1e30f;
                if (c0     > qr1) v2 = -1e30f;
                if (c0 + 1 > qr1) v3 = -1e30f;
            }
            s[nt][0] = v0; s[nt][1] = v1; s[nt][2] = v2; s[nt][3] = v3;
        }

        // online softmax
        float mx0 = -1e30f, mx1 = -1e30f;
#pragma unroll
        for (int nt = 0; nt < 8; nt++) {
            mx0 = fmaxf(mx0, fmaxf(s[nt][0], s[nt][1]));
            mx1 = fmaxf(mx1, fmaxf(s[nt][2], s[nt][3]));
        }
        mx0 = fmaxf(mx0, __shfl_xor_sync(0xffffffffu, mx0, 1));
        mx0 = fmaxf(mx0, __shfl_xor_sync(0xffffffffu, mx0, 2));
        mx1 = fmaxf(mx1, __shfl_xor_sync(0xffffffffu, mx1, 1));
        mx1 = fmaxf(mx1, __shfl_xor_sync(0xffffffffu, mx1, 2));

        const float mn0 = fmaxf(m0, mx0), mn1 = fmaxf(m1, mx1);
        const float a0 = ex2(m0 - mn0), a1 = ex2(m1 - mn1);

        float ls0 = 0.f, ls1 = 0.f;
#pragma unroll
        for (int nt = 0; nt < 8; nt++) {
            const float p0 = ex2(s[nt][0] - mn0);
            const float p1 = ex2(s[nt][1] - mn0);
            const float p2 = ex2(s[nt][2] - mn1);
            const float p3 = ex2(s[nt][3] - mn1);
            ls0 += p0 + p1; ls1 += p2 + p3;
            *(uint32_t*)&Ps[(wq + g) * 72 + nt * 8 + 2 * t]     = h2u(p0, p1);
            *(uint32_t*)&Ps[(wq + g + 8) * 72 + nt * 8 + 2 * t] = h2u(p2, p3);
        }
        ls0 += __shfl_xor_sync(0xffffffffu, ls0, 1);
        ls0 += __shfl_xor_sync(0xffffffffu, ls0, 2);
        ls1 += __shfl_xor_sync(0xffffffffu, ls1, 1);
        ls1 += __shfl_xor_sync(0xffffffffu, ls1, 2);
        l0 = l0 * a0 + ls0;
        l1 = l1 * a1 + ls1;
        m0 = mn0; m1 = mn1;

#pragma unroll
        for (int nt = 0; nt < 16; nt++) {
            o[nt][0] *= a0; o[nt][1] *= a0;
            o[nt][2] *= a1; o[nt][3] *= a1;
        }
        __syncwarp();

        // O += P V : warp 16q x 128d
#pragma unroll
        for (int ks = 0; ks < 4; ks++) {
            uint32_t pa[4];
            ldm4(psb + (uint32_t)((wq + a_row) * 72 + ks * 16 + a_col8) * 2u,
                 pa);
#pragma unroll
            for (int j = 0; j < 8; j++) {
                uint32_t vb[4];
                ldm4(vs_b + (uint32_t)(((2 * j + b_rgrp) * 8 + b_row) * 72
                                       + ks * 16 + b_col8) * 2u, vb);
                mma16(o[2 * j],     pa, vb[0], vb[1]);
                mma16(o[2 * j + 1], pa, vb[2], vb[3]);
            }
        }
        __syncthreads();
    }

    // epilogue
    const float il0 = 1.f / l0, il1 = 1.f / l1;
    const int r0 = qb + wq + g, r1 = r0 + 8;
#pragma unroll
    for (int nt = 0; nt < 16; nt++) {
        const int c = nt * 8 + 2 * t;
        *(uint32_t*)&Og[(size_t)r0 * HDc + c] = h2u(o[nt][0] * il0, o[nt][1] * il0);
        *(uint32_t*)&Og[(size_t)r1 * HDc + c] = h2u(o[nt][2] * il1, o[nt][3] * il1);
    }
}

// ---------------------------------------------------------------------------
extern "C" void kernel_launch(void* const* d_in, const int* in_sizes, int n_in,
                              void* d_out, int out_size)
{
    const float* x  = (const float*)d_in[0];
    const float* y  = (const float*)d_in[1];
    const float* Wq = (const float*)d_in[2];
    const float* bq = (const float*)d_in[3];
    const float* Wk = (const float*)d_in[4];
    const float* bk = (const float*)d_in[5];
    const float* Wv = (const float*)d_in[6];
    const float* bv = (const float*)d_in[7];
    const float* Wo = (const float*)d_in[8];
    const float* bo = (const float*)d_in[9];
    float* out = (float*)d_out;

    cudaFuncSetAttribute(flash_attn,
                         cudaFuncAttributeMaxDynamicSharedMemorySize, FLASH_SMEM);
    cudaFuncSetAttribute(gemm_h<0>,
                         cudaFuncAttributeMaxDynamicSharedMemorySize, GEMM_SMEM);
    cudaFuncSetAttribute(gemm_h<1>,
                         cudaFuncAttributeMaxDynamicSharedMemorySize, GEMM_SMEM);
    cudaFuncSetAttribute(gemm_h<2>,
                         cudaFuncAttributeMaxDynamicSharedMemorySize, GEMM_SMEM);

    __half* gx; cudaGetSymbolAddress((void**)&gx, g_xh);
    __half* gy; cudaGetSymbolAddress((void**)&gy, g_yh);
    __half* gw; cudaGetSymbolAddress((void**)&gw, g_wh);
    __half* gq; cudaGetSymbolAddress((void**)&gq, g_qh);
    __half* gk; cudaGetSymbolAddress((void**)&gk, g_kh);
    __half* gvt; cudaGetSymbolAddress((void**)&gvt, g_vt);
    __half* gc; cudaGetSymbolAddress((void**)&gc, g_ch);

    // 1. convert inputs + weights to fp16
    const int nXY4 = (Mc * Dc) / 4;
    const int nW4  = (Dc * Dc) / 4;
    conv_h2<<<dim3((nXY4 + 255)/256, 2), 256>>>(
        (const float4*)x, (uint2*)gx, (const float4*)y, (uint2*)gy, nXY4);
    conv_h4<<<dim3((nW4 + 255)/256, 4), 256>>>(
        (const float4*)Wq, (const float4*)Wk, (const float4*)Wv,
        (const float4*)Wo, (uint2*)gw, nW4);

    // 2. projections
    dim3 gblk(256);
    dim3 ggrid(Dc/128, Mc/128);   // (8, 64) = 512 CTAs
    gemm_h<0><<<ggrid, gblk, GEMM_SMEM>>>(gx, gw + 0*Dc*Dc, bq, gq,  nullptr);
    gemm_h<0><<<ggrid, gblk, GEMM_SMEM>>>(gy, gw + 1*Dc*Dc, bk, gk,  nullptr);
    gemm_h<2><<<ggrid, gblk, GEMM_SMEM>>>(gy, gw + 2*Dc*Dc, bv, gvt, nullptr);

    // 3. attention
    dim3 fgrid(Tc/64, Bc*Hc);     // (32, 32) = 1024 CTAs
    flash_attn<<<fgrid, dim3(128), FLASH_SMEM>>>();

    // 4. output projection
    gemm_h<1><<<ggrid, gblk, GEMM_SMEM>>>(gc, gw + 3*Dc*Dc, bo, nullptr, out);
}

// round 9
// speedup vs baseline: 7.6820x; 1.0172x over previous
#include <cuda_runtime.h>
#include <cuda_fp16.h>
#include <math.h>
#include <stdint.h>

#define Bc  4
#define Tc  2048
#define Dc  1024
#define Hc  8
#define HDc 128
#define Mc  (Bc*Tc)

// Scratch (fp16)
__device__ __half g_qh[Bc*Tc*Dc];           // [B,H,T,HD]
__device__ __half g_kh[Bc*Tc*Dc];           // [B,H,T,HD]
__device__ __half g_vt[Bc*Tc*Dc];           // [B,H,HD,T]  (V transposed)
__device__ __half g_ch[Bc*Tc*Dc];           // ctx [B,H,T,HD]
__device__ __half g_xh[Bc*Tc*Dc];
__device__ __half g_yh[Bc*Tc*Dc];
__device__ __half g_wh[4][Dc*Dc];

// ---------------------------------------------------------------------------
// helpers
// ---------------------------------------------------------------------------
__device__ __forceinline__ uint32_t smem_u32(const void* p) {
    uint32_t a;
    asm("{ .reg .u64 t; cvta.to.shared.u64 t, %1; cvt.u32.u64 %0, t; }"
        : "=r"(a) : "l"(p));
    return a;
}
__device__ __forceinline__ float ex2(float x) {
    float y;
    asm("ex2.approx.f32 %0, %1;" : "=f"(y) : "f"(x));
    return y;
}
__device__ __forceinline__ uint32_t h2u(float a, float b) {
    __half2 h = __floats2half2_rn(a, b);
    return *(uint32_t*)&h;
}
__device__ __forceinline__ void cp16(uint32_t dst, const void* src) {
    asm volatile("cp.async.cg.shared.global [%0], [%1], 16;" :: "r"(dst), "l"(src));
}
#define CP_COMMIT() asm volatile("cp.async.commit_group;" ::: "memory")
#define CP_WAIT1()  asm volatile("cp.async.wait_group 1;" ::: "memory")
#define CP_WAIT0()  asm volatile("cp.async.wait_group 0;" ::: "memory")

// ldmatrix x4 (b16, non-trans)
__device__ __forceinline__ void ldm4(uint32_t addr, uint32_t* r) {
    asm volatile("ldmatrix.sync.aligned.m8n8.x4.shared.b16 {%0,%1,%2,%3}, [%4];"
                 : "=r"(r[0]), "=r"(r[1]), "=r"(r[2]), "=r"(r[3]) : "r"(addr));
}

// m16n8k16 fp16 MMA, f32 accumulate in place.
__device__ __forceinline__ void mma16(float* d, const uint32_t* a,
                                      uint32_t b0, uint32_t b1) {
    asm volatile(
        "mma.sync.aligned.m16n8k16.row.col.f32.f16.f16.f32 "
        "{%0,%1,%2,%3}, {%4,%5,%6,%7}, {%8,%9}, {%0,%1,%2,%3};"
        : "+f"(d[0]), "+f"(d[1]), "+f"(d[2]), "+f"(d[3])
        : "r"(a[0]), "r"(a[1]), "r"(a[2]), "r"(a[3]), "r"(b0), "r"(b1));
}

// ---------------------------------------------------------------------------
// fp32 -> fp16 converts (2 fused launches)
// ---------------------------------------------------------------------------
__global__ void conv_h2(const float4* __restrict__ a, uint2* __restrict__ oa,
                        const float4* __restrict__ b, uint2* __restrict__ ob,
                        int n4) {
    int i = blockIdx.x * blockDim.x + threadIdx.x;
    const float4* s = blockIdx.y ? b : a;
    uint2* d = blockIdx.y ? ob : oa;
    if (i < n4) {
        float4 v = s[i];
        uint2 o;
        o.x = h2u(v.x, v.y);
        o.y = h2u(v.z, v.w);
        d[i] = o;
    }
}

__global__ void conv_h4(const float4* __restrict__ w0, const float4* __restrict__ w1,
                        const float4* __restrict__ w2, const float4* __restrict__ w3,
                        uint2* __restrict__ o0, int n4) {
    int i = blockIdx.x * blockDim.x + threadIdx.x;
    const float4* s = (blockIdx.y == 0) ? w0 : (blockIdx.y == 1) ? w1
                      : (blockIdx.y == 2) ? w2 : w3;
    uint2* d = o0 + (size_t)blockIdx.y * (Dc * Dc / 4);
    if (i < n4) {
        float4 v = s[i];
        uint2 o;
        o.x = h2u(v.x, v.y);
        o.y = h2u(v.z, v.w);
        d[i] = o;
    }
}

// ---------------------------------------------------------------------------
// fp16 warp-MMA GEMM: out[m,n] = sum_k A[m,k]*W[n,k] + bias[n]
// CTA tile 128x128, 8 warps (warp 32x64), K-chunk 32 halves, 3-stage cp.async,
// ldmatrix fragments, 2 CTAs/SM, ONE __syncthreads per k-iteration.
// Pipeline: prologue issues chunks 0,1. Iter i: wait(chunk i ready) -> sync ->
// issue chunk i+2 into stage (i+2)%3 (== stage read at iter i-1) -> compute.
// ---------------------------------------------------------------------------
#define GEMM_SMEM (3*20480)

template<int MODE>
__global__ __launch_bounds__(256, 2)
void gemm_h(const __half* __restrict__ A, const __half* __restrict__ Wg,
            const float* __restrict__ bias, __half* __restrict__ outh,
            float* __restrict__ outf)
{
    extern __shared__ __align__(16) char smemc[];
    const uint32_t sb = smem_u32(smemc);

    const int tid = threadIdx.x;
    const int wid = tid >> 5, lane = tid & 31;
    const int g = lane >> 2, t = lane & 3;
    const int wm = (wid & 3) * 32, wn = (wid >> 2) * 64;
    const int bn = blockIdx.x * 128, bm = blockIdx.y * 128;

    const int a_row = lane & 15, a_col8 = ((lane >> 4) & 1) * 8;
    const int b_rgrp = (lane >> 4) & 1, b_row = lane & 7;
    const int b_col8 = ((lane >> 3) & 1) * 8;

    auto issue = [&](int stg, int k0) {
        const uint32_t da = sb + (uint32_t)(stg * 20480);
        const uint32_t db = da + 10240u;
#pragma unroll
        for (int it = 0; it < 2; it++) {
            const int idx = tid + it * 256;          // 0..511
            const int row = idx >> 2, s = idx & 3;
            const __half* src;
            if (MODE == 1) {
                const int m = bm + row, b = m >> 11, tt = m & 2047;
                const int kg = k0 + s * 8;
                const int h = kg >> 7, d = kg & 127;
                src = A + (((size_t)(b * Hc + h) * Tc + tt) * HDc + d);
            } else {
                src = A + (size_t)(bm + row) * Dc + k0 + s * 8;
            }
            cp16(da + (uint32_t)(row * 40 + s * 8) * 2u, src);
        }
#pragma unroll
        for (int it = 0; it < 2; it++) {
            const int idx = tid + it * 256;
            const int row = idx >> 2, s = idx & 3;
            cp16(db + (uint32_t)(row * 40 + s * 8) * 2u,
                 Wg + (size_t)(bn + row) * Dc + k0 + s * 8);
        }
        CP_COMMIT();
    };

    float c[2][8][4];
#pragma unroll
    for (int mt = 0; mt < 2; mt++)
#pragma unroll
        for (int nt = 0; nt < 8; nt++)
#pragma unroll
            for (int j = 0; j < 4; j++) c[mt][nt][j] = 0.f;

    issue(0, 0); issue(1, 32);

    for (int i = 0; i < 32; i++) {
        if (i == 31) { CP_WAIT0(); } else { CP_WAIT1(); }
        __syncthreads();
        if (i + 2 < 32) issue((i + 2) % 3, (i + 2) * 32);

        const uint32_t as = sb + (uint32_t)((i % 3) * 20480);
        const uint32_t bs = as + 10240u;

#pragma unroll
        for (int ks = 0; ks < 2; ks++) {
            const int kk = ks * 16;
            uint32_t a[2][4];
#pragma unroll
            for (int mt = 0; mt < 2; mt++)
                ldm4(as + (uint32_t)((wm + mt * 16 + a_row) * 40 + kk + a_col8) * 2u,
                     a[mt]);
#pragma unroll
            for (int j = 0; j < 4; j++) {
                uint32_t br[4];
                ldm4(bs + (uint32_t)((wn + (2 * j + b_rgrp) * 8 + b_row) * 40
                                     + kk + b_col8) * 2u, br);
#pragma unroll
                for (int mt = 0; mt < 2; mt++) {
                    mma16(c[mt][2 * j],     a[mt], br[0], br[1]);
                    mma16(c[mt][2 * j + 1], a[mt], br[2], br[3]);
                }
            }
        }
    }
    __syncthreads();   // protect smem reuse by MODE==2 epilogue staging

    const int b0i_base = bm >> 11, t0 = bm & 2047;
    const int h = bn >> 7;

    if (MODE == 2) {
        __half* Ts = (__half*)smemc;          // [128 n][136] halves
#pragma unroll
        for (int mt = 0; mt < 2; mt++) {
            const int r0l = wm + mt * 16 + g, r1l = r0l + 8;
#pragma unroll
            for (int nt = 0; nt < 8; nt++) {
                const int cl = wn + nt * 8 + 2 * t;
                const float bx = __ldg(bias + bn + cl);
                const float by = __ldg(bias + bn + cl + 1);
                Ts[(cl    ) * 136 + r0l] = __float2half_rn(c[mt][nt][0] + bx);
                Ts[(cl + 1) * 136 + r0l] = __float2half_rn(c[mt][nt][1] + by);
                Ts[(cl    ) * 136 + r1l] = __float2half_rn(c[mt][nt][2] + bx);
                Ts[(cl + 1) * 136 + r1l] = __float2half_rn(c[mt][nt][3] + by);
            }
        }
        __syncthreads();
#pragma unroll
        for (int it = 0; it < 8; it++) {
            const int idx = tid + it * 256;          // 0..2047
            const int row = idx >> 4, s = idx & 15;
            const uint4 v = *(const uint4*)&Ts[row * 136 + s * 8];
            *(uint4*)&outh[(((size_t)(b0i_base * Hc + h) * HDc + row)
                            * Tc) + t0 + s * 8] = v;
        }
        return;
    }

#pragma unroll
    for (int mt = 0; mt < 2; mt++) {
        const int r0 = bm + wm + mt * 16 + g;
        const int r1 = r0 + 8;
#pragma unroll
        for (int nt = 0; nt < 8; nt++) {
            const int cl = wn + nt * 8 + 2 * t;
            const int col = bn + cl;
            const float bx = __ldg(bias + col), by = __ldg(bias + col + 1);
            const float v00 = c[mt][nt][0] + bx, v01 = c[mt][nt][1] + by;
            const float v10 = c[mt][nt][2] + bx, v11 = c[mt][nt][3] + by;
            if (MODE == 0) {
                const int b0i = r0 >> 11, t0i = r0 & 2047;
                const int b1i = r1 >> 11, t1i = r1 & 2047;
                *(uint32_t*)&outh[(((size_t)(b0i * Hc + h) * Tc + t0i) * HDc) + cl]
                    = h2u(v00, v01);
                *(uint32_t*)&outh[(((size_t)(b1i * Hc + h) * Tc + t1i) * HDc) + cl]
                    = h2u(v10, v11);
            } else {
                *(float2*)&outf[(size_t)r0 * Dc + col] = make_float2(v00, v01);
                *(float2*)&outf[(size_t)r1 * Dc + col] = make_float2(v10, v11);
            }
        }
    }
}

// ---------------------------------------------------------------------------
// Flash attention fp16: 128 threads / 4 warps; Q tile 64 (warp 16 q-rows),
// K tile 64; ldmatrix fragments; double-buffered K/V; reversed qt order;
// ONE __syncthreads per k-tile (wait -> sync -> issue next -> compute).
// ---------------------------------------------------------------------------
#define FLASH_SMEM 80896
#define HK0  0
#define HK1  8704
#define HV0  17408
#define HV1  26624
#define HPS  35840

__global__ __launch_bounds__(128, 2)
void flash_attn()
{
    extern __shared__ __align__(16) __half fsm[];
    const uint32_t sb = smem_u32(fsm);

    const int bh  = blockIdx.y;
    const int qt  = gridDim.x - 1 - blockIdx.x;    // longest blocks first
    const int qb  = qt * 64;
    const int tid = threadIdx.x;
    const int wid = tid >> 5, lane = tid & 31;
    const int g = lane >> 2, t = lane & 3;
    const int wq = wid * 16;

    const int a_row = lane & 15, a_col8 = ((lane >> 4) & 1) * 8;
    const int b_rgrp = (lane >> 4) & 1, b_row = lane & 7;
    const int b_col8 = ((lane >> 3) & 1) * 8;

    const __half* Qg  = g_qh + (size_t)bh * Tc * HDc;
    const __half* Kg  = g_kh + (size_t)bh * Tc * HDc;
    const __half* Vtg = g_vt + (size_t)bh * HDc * Tc;
    __half*       Og  = g_ch + (size_t)bh * Tc * HDc;

    __half* Ps = fsm + HPS;
    const uint32_t psb = sb + HPS * 2u;

    // Q fragments, held all loop
    uint32_t qf[8][4];
    {
        const int r0 = qb + wq + g, r1 = r0 + 8;
#pragma unroll
        for (int ds = 0; ds < 8; ds++) {
            qf[ds][0] = *(const uint32_t*)&Qg[(size_t)r0 * HDc + ds * 16 + 2 * t];
            qf[ds][1] = *(const uint32_t*)&Qg[(size_t)r1 * HDc + ds * 16 + 2 * t];
            qf[ds][2] = *(const uint32_t*)&Qg[(size_t)r0 * HDc + ds * 16 + 8 + 2 * t];
            qf[ds][3] = *(const uint32_t*)&Qg[(size_t)r1 * HDc + ds * 16 + 8 + 2 * t];
        }
    }

    float o[16][4];
#pragma unroll
    for (int nt = 0; nt < 16; nt++)
#pragma unroll
        for (int j = 0; j < 4; j++) o[nt][j] = 0.f;

    float m0 = -1e30f, m1 = -1e30f, l0 = 0.f, l1 = 0.f;
    const int ktmax = qt;

    auto issue_kv = [&](int buf, int kt) {
        const int kb = kt * 64;
        const uint32_t kd = sb + (buf ? HK1 : HK0) * 2u;
        const uint32_t vd = sb + (buf ? HV1 : HV0) * 2u;
#pragma unroll
        for (int it = 0; it < 8; it++) {
            const int idx = tid + it * 128;          // 0..1023
            const int c = idx >> 4, s = idx & 15;
            cp16(kd + (uint32_t)(c * 136 + s * 8) * 2u,
                 Kg + (size_t)(kb + c) * HDc + s * 8);
        }
#pragma unroll
        for (int it = 0; it < 8; it++) {
            const int idx = tid + it * 128;          // 0..1023
            const int d = idx >> 3, s = idx & 7;
            cp16(vd + (uint32_t)(d * 72 + s * 8) * 2u,
                 Vtg + (size_t)d * Tc + kb + s * 8);
        }
        CP_COMMIT();
    };

    issue_kv(0, 0);

    const float Csc = 0.12751743342f;   // (1/sqrt(128)) * log2(e)

    for (int kt = 0; kt <= ktmax; kt++) {
        const int cur = kt & 1;
        CP_WAIT0();
        __syncthreads();               // data visible + all warps done with
                                       // buffer 1-cur (read during kt-1)
        if (kt < ktmax) issue_kv(1 - cur, kt + 1);

        const uint32_t ks_b = sb + (cur ? HK1 : HK0) * 2u;
        const uint32_t vs_b = sb + (cur ? HV1 : HV0) * 2u;
        const int kb = kt * 64;

        // S = Q K^T : warp 16q x 64c
        float s[8][4];
#pragma unroll
        for (int nt = 0; nt < 8; nt++)
#pragma unroll
            for (int j = 0; j < 4; j++) s[nt][j] = 0.f;

#pragma unroll
        for (int ds = 0; ds < 8; ds++) {
#pragma unroll
            for (int j = 0; j < 4; j++) {
                uint32_t br[4];
                ldm4(ks_b + (uint32_t)(((2 * j + b_rgrp) * 8 + b_row) * 136
                                       + ds * 16 + b_col8) * 2u, br);
                mma16(s[2 * j],     qf[ds], br[0], br[1]);
                mma16(s[2 * j + 1], qf[ds], br[2], br[3]);
            }
        }

        // scale + causal mask (diagonal tile only)
        const int qr0 = qb + wq + g, qr1 = qr0 + 8;
        const bool needm = (kt == qt);
#pragma unroll
        for (int nt = 0; nt < 8; nt++) {
            const int c0 = kb + nt * 8 + 2 * t;
            float v0 = s[nt][0] * Csc, v1 = s[nt][1] * Csc;
            float v2 = s[nt][2] * Csc, v3 = s[nt][3] * Csc;
            if (needm) {
                if (c0     > qr0) v0 = -1e30f;
                if (c0 + 1 > qr0) v1 = -1e30f;
                if (c0     > qr1) v2 = -1e30f;
                if (c0 + 1 > qr1) v3 = -1e30f;
            }
            s[nt][0] = v0; s[nt][1] = v1; s[nt][2] = v2; s[nt][3] = v3;
        }

        // online softmax
        float mx0 = -1e30f, mx1 = -1e30f;
#pragma unroll
        for (int nt = 0; nt < 8; nt++) {
            mx0 = fmaxf(mx0, fmaxf(s[nt][0], s[nt][1]));
            mx1 = fmaxf(mx1, fmaxf(s[nt][2], s[nt][3]));
        }
        mx0 = fmaxf(mx0, __shfl_xor_sync(0xffffffffu, mx0, 1));
        mx0 = fmaxf(mx0, __shfl_xor_sync(0xffffffffu, mx0, 2));
        mx1 = fmaxf(mx1, __shfl_xor_sync(0xffffffffu, mx1, 1));
        mx1 = fmaxf(mx1, __shfl_xor_sync(0xffffffffu, mx1, 2));

        const float mn0 = fmaxf(m0, mx0), mn1 = fmaxf(m1, mx1);
        const float a0 = ex2(m0 - mn0), a1 = ex2(m1 - mn1);

        float ls0 = 0.f, ls1 = 0.f;
#pragma unroll
        for (int nt = 0; nt < 8; nt++) {
            const float p0 = ex2(s[nt][0] - mn0);
            const float p1 = ex2(s[nt][1] - mn0);
            const float p2 = ex2(s[nt][2] - mn1);
            const float p3 = ex2(s[nt][3] - mn1);
            ls0 += p0 + p1; ls1 += p2 + p3;
            *(uint32_t*)&Ps[(wq + g) * 72 + nt * 8 + 2 * t]     = h2u(p0, p1);
            *(uint32_t*)&Ps[(wq + g + 8) * 72 + nt * 8 + 2 * t] = h2u(p2, p3);
        }
        ls0 += __shfl_xor_sync(0xffffffffu, ls0, 1);
        ls0 += __shfl_xor_sync(0xffffffffu, ls0, 2);
        ls1 += __shfl_xor_sync(0xffffffffu, ls1, 1);
        ls1 += __shfl_xor_sync(0xffffffffu, ls1, 2);
        l0 = l0 * a0 + ls0;
        l1 = l1 * a1 + ls1;
        m0 = mn0; m1 = mn1;

#pragma unroll
        for (int nt = 0; nt < 16; nt++) {
            o[nt][0] *= a0; o[nt][1] *= a0;
            o[nt][2] *= a1; o[nt][3] *= a1;
        }
        __syncwarp();    // Ps stores (cross-lane) visible to ldmatrix

        // O += P V : warp 16q x 128d
#pragma unroll
        for (int ks = 0; ks < 4; ks++) {
            uint32_t pa[4];
            ldm4(psb + (uint32_t)((wq + a_row) * 72 + ks * 16 + a_col8) * 2u,
                 pa);
#pragma unroll
            for (int j = 0; j < 8; j++) {
                uint32_t vb[4];
                ldm4(vs_b + (uint32_t)(((2 * j + b_rgrp) * 8 + b_row) * 72
                                       + ks * 16 + b_col8) * 2u, vb);
                mma16(o[2 * j],     pa, vb[0], vb[1]);
                mma16(o[2 * j + 1], pa, vb[2], vb[3]);
            }
        }
    }

    // epilogue
    const float il0 = 1.f / l0, il1 = 1.f / l1;
    const int r0 = qb + wq + g, r1 = r0 + 8;
#pragma unroll
    for (int nt = 0; nt < 16; nt++) {
        const int c = nt * 8 + 2 * t;
        *(uint32_t*)&Og[(size_t)r0 * HDc + c] = h2u(o[nt][0] * il0, o[nt][1] * il0);
        *(uint32_t*)&Og[(size_t)r1 * HDc + c] = h2u(o[nt][2] * il1, o[nt][3] * il1);
    }
}

// ---------------------------------------------------------------------------
extern "C" void kernel_launch(void* const* d_in, const int* in_sizes, int n_in,
                              void* d_out, int out_size)
{
    const float* x  = (const float*)d_in[0];
    const float* y  = (const float*)d_in[1];
    const float* Wq = (const float*)d_in[2];
    const float* bq = (const float*)d_in[3];
    const float* Wk = (const float*)d_in[4];
    const float* bk = (const float*)d_in[5];
    const float* Wv = (const float*)d_in[6];
    const float* bv = (const float*)d_in[7];
    const float* Wo = (const float*)d_in[8];
    const float* bo = (const float*)d_in[9];
    float* out = (float*)d_out;

    cudaFuncSetAttribute(flash_attn,
                         cudaFuncAttributeMaxDynamicSharedMemorySize, FLASH_SMEM);
    cudaFuncSetAttribute(gemm_h<0>,
                         cudaFuncAttributeMaxDynamicSharedMemorySize, GEMM_SMEM);
    cudaFuncSetAttribute(gemm_h<1>,
                         cudaFuncAttributeMaxDynamicSharedMemorySize, GEMM_SMEM);
    cudaFuncSetAttribute(gemm_h<2>,
                         cudaFuncAttributeMaxDynamicSharedMemorySize, GEMM_SMEM);

    __half* gx; cudaGetSymbolAddress((void**)&gx, g_xh);
    __half* gy; cudaGetSymbolAddress((void**)&gy, g_yh);
    __half* gw; cudaGetSymbolAddress((void**)&gw, g_wh);
    __half* gq; cudaGetSymbolAddress((void**)&gq, g_qh);
    __half* gk; cudaGetSymbolAddress((void**)&gk, g_kh);
    __half* gvt; cudaGetSymbolAddress((void**)&gvt, g_vt);
    __half* gc; cudaGetSymbolAddress((void**)&gc, g_ch);

    // 1. convert inputs + weights to fp16
    const int nXY4 = (Mc * Dc) / 4;
    const int nW4  = (Dc * Dc) / 4;
    conv_h2<<<dim3((nXY4 + 255)/256, 2), 256>>>(
        (const float4*)x, (uint2*)gx, (const float4*)y, (uint2*)gy, nXY4);
    conv_h4<<<dim3((nW4 + 255)/256, 4), 256>>>(
        (const float4*)Wq, (const float4*)Wk, (const float4*)Wv,
        (const float4*)Wo, (uint2*)gw, nW4);

    // 2. projections
    dim3 gblk(256);
    dim3 ggrid(Dc/128, Mc/128);   // (8, 64) = 512 CTAs
    gemm_h<0><<<ggrid, gblk, GEMM_SMEM>>>(gx, gw + 0*Dc*Dc, bq, gq,  nullptr);
    gemm_h<0><<<ggrid, gblk, GEMM_SMEM>>>(gy, gw + 1*Dc*Dc, bk, gk,  nullptr);
    gemm_h<2><<<ggrid, gblk, GEMM_SMEM>>>(gy, gw + 2*Dc*Dc, bv, gvt, nullptr);

    // 3. attention
    dim3 fgrid(Tc/64, Bc*Hc);     // (32, 32) = 1024 CTAs
    flash_attn<<<fgrid, dim3(128), FLASH_SMEM>>>();

    // 4. output projection
    gemm_h<1><<<ggrid, gblk, GEMM_SMEM>>>(gc, gw + 3*Dc*Dc, bo, nullptr, out);
}